// round 6
// baseline (speedup 1.0000x reference)
#include <cuda_runtime.h>
#include <math.h>

#define B_  4
#define N_  4096
#define K_  16
#define DP_ 64
#define DM_ 128
#define NPTS (B_*N_)

// Scratch (device globals: no allocation allowed in kernel_launch)
__device__ float g_X [NPTS*DM_];
__device__ float g_Q [NPTS*DM_];
__device__ float g_Kf[NPTS*DM_];
__device__ float g_Vf[NPTS*DM_];
__device__ int   g_idx[NPTS*K_];

// ---------------------------------------------------------------------------
// GEMM micro-kernel: 16 rows (smem, row-major 128 wide) x W(128x128 row-major).
// Thread = output column f. acc[k] += sum_kk A[k][kk] * W[kk][f].
// W row loads are coalesced (f = tid); A loads are broadcast LDS.128.
// ---------------------------------------------------------------------------
__device__ __forceinline__ void gemm16_k128(const float* __restrict__ W, int f,
                                            const float* sA, float acc[16]) {
#pragma unroll 2
    for (int kk = 0; kk < 32; ++kk) {
        float w0 = W[(kk*4+0)*DM_ + f];
        float w1 = W[(kk*4+1)*DM_ + f];
        float w2 = W[(kk*4+2)*DM_ + f];
        float w3 = W[(kk*4+3)*DM_ + f];
#pragma unroll
        for (int k = 0; k < 16; ++k) {
            float4 a = *(const float4*)&sA[k*DM_ + kk*4];
            acc[k] = fmaf(a.x, w0, acc[k]);
            acc[k] = fmaf(a.y, w1, acc[k]);
            acc[k] = fmaf(a.z, w2, acc[k]);
            acc[k] = fmaf(a.w, w3, acc[k]);
        }
    }
}

// ---------------------------------------------------------------------------
// Kernel 1: X = features @ fc1_w + fc1_b   (16384 x 64) @ (64 x 128)
// ---------------------------------------------------------------------------
__global__ __launch_bounds__(128) void fc1_kernel(const float* __restrict__ feat,
                                                  const float* __restrict__ W,
                                                  const float* __restrict__ bias) {
    __shared__ __align__(16) float sA[16*64];
    int tid = threadIdx.x;
    int r0  = blockIdx.x * 16;
    for (int i = tid; i < 16*64; i += 128) {
        int r = i >> 6, c = i & 63;
        sA[i] = feat[(r0 + r)*64 + c];
    }
    __syncthreads();
    float acc[16];
    float bf = bias[tid];
#pragma unroll
    for (int k = 0; k < 16; ++k) acc[k] = bf;
#pragma unroll 2
    for (int kk = 0; kk < 16; ++kk) {
        float w0 = W[(kk*4+0)*DM_ + tid];
        float w1 = W[(kk*4+1)*DM_ + tid];
        float w2 = W[(kk*4+2)*DM_ + tid];
        float w3 = W[(kk*4+3)*DM_ + tid];
#pragma unroll
        for (int k = 0; k < 16; ++k) {
            float4 a = *(const float4*)&sA[k*64 + kk*4];
            acc[k] = fmaf(a.x, w0, acc[k]);
            acc[k] = fmaf(a.y, w1, acc[k]);
            acc[k] = fmaf(a.z, w2, acc[k]);
            acc[k] = fmaf(a.w, w3, acc[k]);
        }
    }
#pragma unroll
    for (int k = 0; k < 16; ++k) g_X[(r0 + k)*DM_ + tid] = acc[k];
}

// ---------------------------------------------------------------------------
// Kernel 2: Q = X@wq, K = X@wk, V = X@wv  (no bias)
// ---------------------------------------------------------------------------
__global__ __launch_bounds__(128) void qkv_kernel(const float* __restrict__ wq,
                                                  const float* __restrict__ wk,
                                                  const float* __restrict__ wv) {
    __shared__ __align__(16) float sA[16*DM_];
    int tid = threadIdx.x;
    int r0  = blockIdx.x * 16;
    for (int i = tid; i < 16*DM_; i += 128) sA[i] = g_X[r0*DM_ + i];
    __syncthreads();
    {
        float acc[16];
#pragma unroll
        for (int k = 0; k < 16; ++k) acc[k] = 0.f;
        gemm16_k128(wq, tid, sA, acc);
#pragma unroll
        for (int k = 0; k < 16; ++k) g_Q[(r0 + k)*DM_ + tid] = acc[k];
    }
    {
        float acc[16];
#pragma unroll
        for (int k = 0; k < 16; ++k) acc[k] = 0.f;
        gemm16_k128(wk, tid, sA, acc);
#pragma unroll
        for (int k = 0; k < 16; ++k) g_Kf[(r0 + k)*DM_ + tid] = acc[k];
    }
    {
        float acc[16];
#pragma unroll
        for (int k = 0; k < 16; ++k) acc[k] = 0.f;
        gemm16_k128(wv, tid, sA, acc);
#pragma unroll
        for (int k = 0; k < 16; ++k) g_Vf[(r0 + k)*DM_ + tid] = acc[k];
    }
}

// ---------------------------------------------------------------------------
// Kernel 3: stable top-16 KNN per query (matches stable argsort order).
// One block = 128 queries of one batch; batch xyz in smem (48 KB).
// Strict-< insertion while scanning m ascending == stable tie-break.
// ---------------------------------------------------------------------------
__global__ __launch_bounds__(128) void knn_kernel(const float* __restrict__ xyz) {
    __shared__ float sx[N_];
    __shared__ float sy[N_];
    __shared__ float sz[N_];
    int b    = blockIdx.x >> 5;   // 32 blocks per batch
    int qblk = blockIdx.x & 31;
    int tid  = threadIdx.x;
    const float* xb = xyz + (size_t)b * N_ * 3;
    for (int m = tid; m < N_; m += 128) {
        sx[m] = xb[m*3+0]; sy[m] = xb[m*3+1]; sz[m] = xb[m*3+2];
    }
    __syncthreads();

    int q = qblk * 128 + tid;
    float qx = sx[q], qy = sy[q], qz = sz[q];
    float qsq = qx*qx + qy*qy + qz*qz;

    float dist[16]; int idx[16];
#pragma unroll
    for (int i = 0; i < 16; ++i) { dist[i] = 3.4e38f; idx[i] = N_; }
    float worst = 3.4e38f;

    for (int m = 0; m < N_; ++m) {
        float mx = sx[m], my = sy[m], mz = sz[m];
        float msq = mx*mx + my*my + mz*mz;
        float dot = qx*mx + qy*my + qz*mz;
        float d   = qsq + msq - 2.0f*dot;
        if (d < worst) {
            float dd = d; int ii = m;
#pragma unroll
            for (int i = 0; i < 16; ++i) {
                if (dd < dist[i]) {
                    float td = dist[i]; dist[i] = dd; dd = td;
                    int   ti = idx[i];  idx[i]  = ii; ii = ti;
                }
            }
            worst = dist[15];
        }
    }
    int* op = g_idx + (size_t)(b*N_ + q) * K_;
#pragma unroll
    for (int i = 0; i < 16; ++i) op[i] = idx[i];
}

// ---------------------------------------------------------------------------
// Kernel 4: fused per-point transformer block.
// One block = one point (b, n); 128 threads = 128 output channels.
// k-axis (16 neighbors) lives in per-thread accumulators -> thread-local
// softmax over k.
// ---------------------------------------------------------------------------
__global__ __launch_bounds__(128) void fused_kernel(
    const float* __restrict__ xyz,  const float* __restrict__ feat,
    const float* __restrict__ d1w,  const float* __restrict__ d1b,
    const float* __restrict__ d2w,  const float* __restrict__ d2b,
    const float* __restrict__ g1w,  const float* __restrict__ g1b,
    const float* __restrict__ g2w,  const float* __restrict__ g2b,
    const float* __restrict__ simw, const float* __restrict__ simb,
    const float* __restrict__ fc2w, const float* __restrict__ fc2b,
    float* __restrict__ out_res,    float* __restrict__ out_attn)
{
    __shared__ __align__(16) float sK[16*DM_];  // gathered k -> then (q - k)
    __shared__ __align__(16) float sV[16*DM_];
    __shared__ __align__(16) float sA[16*DM_];  // GEMM input buffer (reused)
    __shared__ float sQ[DM_];
    __shared__ float sRed[DM_];
    __shared__ float sSim[16];
    __shared__ float sKn[16];
    __shared__ float sRp[16][3];
    __shared__ int   sIdx[16];
    __shared__ float sQn;

    int tid = threadIdx.x;
    int p   = blockIdx.x;           // b*N + n
    int b   = p >> 12;
    int n   = p & (N_ - 1);

    if (tid < 16) sIdx[tid] = g_idx[(size_t)p * K_ + tid];
    float qf = g_Q[(size_t)p * DM_ + tid];
    sQ[tid] = qf;
    __syncthreads();

    // gather k, v rows (each row is a coalesced 512B read)
#pragma unroll
    for (int k = 0; k < 16; ++k) {
        int id = sIdx[k];
        size_t base = (size_t)(b*N_ + id) * DM_ + tid;
        sK[k*DM_ + tid] = g_Kf[base];
        sV[k*DM_ + tid] = g_Vf[base];
    }
    if (tid < 16) {
        int id = sIdx[tid];
        const float* xp = xyz + (size_t)(b*N_ + n)  * 3;
        const float* np = xyz + (size_t)(b*N_ + id) * 3;
        sRp[tid][0] = xp[0] - np[0];
        sRp[tid][1] = xp[1] - np[1];
        sRp[tid][2] = xp[2] - np[2];
    }

    // |q|^2 block reduce
    float v2 = qf * qf;
#pragma unroll
    for (int off = 16; off; off >>= 1) v2 += __shfl_down_sync(0xffffffffu, v2, off);
    if ((tid & 31) == 0) sRed[tid >> 5] = v2;
    __syncthreads();                                   // (A): gather + partials visible
    if (tid == 0) {
        float s = sRed[0] + sRed[1] + sRed[2] + sRed[3];
        sQn = fmaxf(sqrtf(s), 1e-8f);
    }

    // per-neighbor dot(q,k) and |k|^2: 8 threads per k
    {
        int k = tid >> 3, lane = tid & 7;
        float dp = 0.f, k2 = 0.f;
#pragma unroll
        for (int i = 0; i < 16; ++i) {
            int f = lane + i*8;
            float kv = sK[k*DM_ + f];
            dp = fmaf(sQ[f], kv, dp);
            k2 = fmaf(kv, kv, k2);
        }
#pragma unroll
        for (int off = 4; off; off >>= 1) {
            dp += __shfl_down_sync(0xffffffffu, dp, off, 8);
            k2 += __shfl_down_sync(0xffffffffu, k2, off, 8);
        }
        if (lane == 0) { sSim[k] = dp; sKn[k] = k2; }
    }
    __syncthreads();                                   // (B)

    if (tid < 16) {
        float kn = fmaxf(sqrtf(sKn[tid]), 1e-8f);
        sSim[tid] = sSim[tid] / (sQn * kn);
    }

    // build pe1 = relu(rel_pos @ d1 + b) into sA, and (q - k) in-place in sK
    {
        float w0 = d1w[tid], w1 = d1w[DM_ + tid], w2 = d1w[2*DM_ + tid];
        float bb = d1b[tid];
#pragma unroll
        for (int k = 0; k < 16; ++k) {
            float vv = fmaf(sRp[k][0], w0, fmaf(sRp[k][1], w1, fmaf(sRp[k][2], w2, bb)));
            sA[k*DM_ + tid] = fmaxf(vv, 0.f);
            sK[k*DM_ + tid] = qf - sK[k*DM_ + tid];
        }
    }
    __syncthreads();                                   // (C)

    // pos_enc = pe1 @ d2 + d2b   (stays in registers for the whole kernel)
    float pos[16];
    {
        float bb = d2b[tid];
#pragma unroll
        for (int k = 0; k < 16; ++k) pos[k] = bb;
        gemm16_k128(d2w, tid, sA, pos);
    }

    // rel = [sim, q-k] @ sim_w + sim_b
    float acc[16];
    {
        float w0 = simw[tid];
        float bb = simb[tid];
#pragma unroll
        for (int k = 0; k < 16; ++k) acc[k] = fmaf(sSim[k], w0, bb);
        gemm16_k128(simw + DM_, tid, sK, acc);   // rows 1..128
    }
    __syncthreads();                                   // (D): sA free

    // t = rel + pos_enc  ->  sA
#pragma unroll
    for (int k = 0; k < 16; ++k) sA[k*DM_ + tid] = acc[k] + pos[k];
    __syncthreads();                                   // (E)

    // h = relu(t @ g1 + b)
    {
        float bb = g1b[tid];
#pragma unroll
        for (int k = 0; k < 16; ++k) acc[k] = bb;
        gemm16_k128(g1w, tid, sA, acc);
    }
    __syncthreads();                                   // (F): sA free
#pragma unroll
    for (int k = 0; k < 16; ++k) sA[k*DM_ + tid] = fmaxf(acc[k], 0.f);
    __syncthreads();                                   // (G)

    // logits = h @ g2 + b
    {
        float bb = g2b[tid];
#pragma unroll
        for (int k = 0; k < 16; ++k) acc[k] = bb;
        gemm16_k128(g2w, tid, sA, acc);
    }

    // softmax over k (thread-local), scaled by 1/sqrt(128)
    const float scale = 1.0f / 11.313708498984760390f;
    float mx = -3.4e38f;
#pragma unroll
    for (int k = 0; k < 16; ++k) { acc[k] *= scale; mx = fmaxf(mx, acc[k]); }
    float ssum = 0.f;
#pragma unroll
    for (int k = 0; k < 16; ++k) { acc[k] = expf(acc[k] - mx); ssum += acc[k]; }
    float inv = 1.0f / ssum;
    float resf = 0.f;
#pragma unroll
    for (int k = 0; k < 16; ++k) {
        float a = acc[k] * inv;
        out_attn[((size_t)p * K_ + k) * DM_ + tid] = a;
        resf = fmaf(a, sV[k*DM_ + tid] + pos[k], resf);
    }
    sRed[tid] = resf;
    __syncthreads();                                   // (H)

    // out = res @ fc2 + fc2_b + features
    if (tid < DP_) {
        float o = fc2b[tid] + feat[(size_t)p * DP_ + tid];
#pragma unroll 4
        for (int f = 0; f < DM_; ++f) o = fmaf(sRed[f], fc2w[f*DP_ + tid], o);
        out_res[(size_t)p * DP_ + tid] = o;
    }
}

// ---------------------------------------------------------------------------
extern "C" void kernel_launch(void* const* d_in, const int* in_sizes, int n_in,
                              void* d_out, int out_size) {
    const float* xyz   = (const float*)d_in[0];
    const float* feats = (const float*)d_in[1];
    const float* fc1w  = (const float*)d_in[2];
    const float* fc1b  = (const float*)d_in[3];
    const float* fc2w  = (const float*)d_in[4];
    const float* fc2b  = (const float*)d_in[5];
    const float* d1w   = (const float*)d_in[6];
    const float* d1b   = (const float*)d_in[7];
    const float* d2w   = (const float*)d_in[8];
    const float* d2b   = (const float*)d_in[9];
    const float* g1w   = (const float*)d_in[10];
    const float* g1b   = (const float*)d_in[11];
    const float* g2w   = (const float*)d_in[12];
    const float* g2b   = (const float*)d_in[13];
    const float* wqw   = (const float*)d_in[14];
    const float* wkw   = (const float*)d_in[15];
    const float* wvw   = (const float*)d_in[16];
    const float* simw  = (const float*)d_in[17];
    const float* simb  = (const float*)d_in[18];

    float* out      = (float*)d_out;
    float* out_res  = out;                       // (B, N, DP)
    float* out_attn = out + (size_t)B_*N_*DP_;   // (B, N, K, DM)

    fc1_kernel<<<NPTS/16, 128>>>(feats, fc1w, fc1b);
    qkv_kernel<<<NPTS/16, 128>>>(wqw, wkw, wvw);
    knn_kernel<<<B_ * (N_/128), 128>>>(xyz);
    fused_kernel<<<NPTS, 128>>>(xyz, feats, d1w, d1b, d2w, d2b,
                                g1w, g1b, g2w, g2b, simw, simb,
                                fc2w, fc2b, out_res, out_attn);
}

// round 7
// speedup vs baseline: 1.3680x; 1.3680x over previous
#include <cuda_runtime.h>
#include <math.h>

#define B_  4
#define N_  4096
#define K_  16
#define DP_ 64
#define DM_ 128
#define NPTS (B_*N_)
#define PAD 20   // col-major tile pad: 20 floats = 80B (16B aligned, odd/32-coprime-ish banks)

// Scratch (device globals: no allocation allowed in kernel_launch)
__device__ float g_X  [NPTS*DM_];
__device__ float g_Q  [NPTS*DM_];
__device__ float g_Kf [NPTS*DM_];
__device__ float g_Vf [NPTS*DM_];
__device__ float g_QS2[NPTS*DM_];
__device__ float g_KS2[NPTS*DM_];
__device__ float g_kn [NPTS];
__device__ int   g_idx[NPTS*K_];
__device__ float g_Wp [DM_*DM_];   // d2_w @ g1_w
__device__ float g_SWG[DM_*DM_];   // sim_w[1:] @ g1_w
__device__ float g_u  [DM_];       // sim_w[0] @ g1_w
__device__ float g_cb [DM_];       // (sim_b + d2_b) @ g1_w + g1_b

// ---------------------------------------------------------------------------
// fp32x2 packed helpers
// ---------------------------------------------------------------------------
__device__ __forceinline__ unsigned long long pk(float x, float y) {
    unsigned long long r;
    asm("mov.b64 %0, {%1, %2};" : "=l"(r) : "f"(x), "f"(y));
    return r;
}
__device__ __forceinline__ void ffma2(unsigned long long& d,
                                      unsigned long long a, unsigned long long b) {
    asm("fma.rn.f32x2 %0, %1, %2, %0;" : "+l"(d) : "l"(a), "l"(b));
}
__device__ __forceinline__ float2 upk(unsigned long long v) {
    float2 r;
    asm("mov.b64 {%0, %1}, %2;" : "=f"(r.x), "=f"(r.y) : "l"(v));
    return r;
}

// ---------------------------------------------------------------------------
// Col-major GEMM micro-kernel: A is 16 rows x 128 cols stored column-major
// (column c at sCM[c*PAD .. c*PAD+15]). Thread = output column f.
// acc2[j] accumulates rows (2j, 2j+1) packed as f32x2.
// Per K-dim: 4 broadcast LDS.128 + 1 LDG + 1 pack + 8 FFMA2.
// ---------------------------------------------------------------------------
__device__ __forceinline__ void gemm_cm(const float* __restrict__ W, int f,
                                        const float* sCM,
                                        unsigned long long acc2[8]) {
#pragma unroll 2
    for (int c = 0; c < DM_; ++c) {
        float w = W[c*DM_ + f];
        unsigned long long w2 = pk(w, w);
        const ulonglong2* col = (const ulonglong2*)(sCM + c*PAD);
#pragma unroll
        for (int j = 0; j < 4; ++j) {
            ulonglong2 a = col[j];
            ffma2(acc2[2*j],   a.x, w2);
            ffma2(acc2[2*j+1], a.y, w2);
        }
    }
}

// ---------------------------------------------------------------------------
// Kernel 0: fold weights: Wp = d2w@g1w, SWG = sim_w[1:]@g1w,
//           u = sim_w[0]@g1w, cb = (sim_b+d2_b)@g1w + g1b
// ---------------------------------------------------------------------------
__global__ __launch_bounds__(128) void wprep_kernel(
    const float* __restrict__ d2w, const float* __restrict__ d2b,
    const float* __restrict__ g1w, const float* __restrict__ g1b,
    const float* __restrict__ simw, const float* __restrict__ simb)
{
    int f = threadIdx.x, i = blockIdx.x;
    if (i < DM_) {
        float a = 0.f, s = 0.f;
        for (int m = 0; m < DM_; ++m) {
            float g = g1w[m*DM_ + f];
            a = fmaf(d2w[i*DM_ + m], g, a);
            s = fmaf(simw[(1+i)*DM_ + m], g, s);
        }
        g_Wp[i*DM_ + f]  = a;
        g_SWG[i*DM_ + f] = s;
    } else {
        float u = 0.f, c = 0.f;
        for (int m = 0; m < DM_; ++m) {
            float g = g1w[m*DM_ + f];
            u = fmaf(simw[m], g, u);
            c = fmaf(simb[m] + d2b[m], g, c);
        }
        g_u[f]  = u;
        g_cb[f] = c + g1b[f];
    }
}

// ---------------------------------------------------------------------------
// Kernel 1: X = features @ fc1_w + fc1_b   (16384 x 64) @ (64 x 128)
// ---------------------------------------------------------------------------
__global__ __launch_bounds__(128) void fc1_kernel(const float* __restrict__ feat,
                                                  const float* __restrict__ W,
                                                  const float* __restrict__ bias) {
    __shared__ __align__(16) float sA[16*64];
    int tid = threadIdx.x;
    int r0  = blockIdx.x * 16;
    for (int i = tid; i < 16*64; i += 128) sA[i] = feat[r0*64 + i];
    __syncthreads();
    float acc[16];
    float bf = bias[tid];
#pragma unroll
    for (int k = 0; k < 16; ++k) acc[k] = bf;
#pragma unroll 2
    for (int kk = 0; kk < 16; ++kk) {
        float w0 = W[(kk*4+0)*DM_ + tid];
        float w1 = W[(kk*4+1)*DM_ + tid];
        float w2 = W[(kk*4+2)*DM_ + tid];
        float w3 = W[(kk*4+3)*DM_ + tid];
#pragma unroll
        for (int k = 0; k < 16; ++k) {
            float4 a = *(const float4*)&sA[k*64 + kk*4];
            acc[k] = fmaf(a.x, w0, acc[k]);
            acc[k] = fmaf(a.y, w1, acc[k]);
            acc[k] = fmaf(a.z, w2, acc[k]);
            acc[k] = fmaf(a.w, w3, acc[k]);
        }
    }
#pragma unroll
    for (int k = 0; k < 16; ++k) g_X[(r0 + k)*DM_ + tid] = acc[k];
}

// ---------------------------------------------------------------------------
// Kernel 2: q/k/v projections + QS2 = q@SWG, KS2 = k@SWG, kn = max(||k||,eps)
// ---------------------------------------------------------------------------
__global__ __launch_bounds__(128) void qkv2_kernel(const float* __restrict__ wq,
                                                   const float* __restrict__ wk,
                                                   const float* __restrict__ wv) {
    __shared__ __align__(16) float sX [DM_*PAD];
    __shared__ __align__(16) float sQc[DM_*PAD];
    __shared__ __align__(16) float sKc[DM_*PAD];
    int tid = threadIdx.x;
    int r0  = blockIdx.x * 16;

    for (int i = tid; i < 16*DM_; i += 128) {
        int r = i >> 7, c = i & 127;
        sX[c*PAD + r] = g_X[r0*DM_ + i];
    }
    __syncthreads();

    unsigned long long acc2[8];
    // q
#pragma unroll
    for (int j = 0; j < 8; ++j) acc2[j] = 0ull;
    gemm_cm(wq, tid, sX, acc2);
#pragma unroll
    for (int j = 0; j < 8; ++j) {
        float2 v = upk(acc2[j]);
        g_Q[(r0 + 2*j  )*DM_ + tid] = v.x;
        g_Q[(r0 + 2*j+1)*DM_ + tid] = v.y;
        sQc[tid*PAD + 2*j]   = v.x;
        sQc[tid*PAD + 2*j+1] = v.y;
    }
    // k
#pragma unroll
    for (int j = 0; j < 8; ++j) acc2[j] = 0ull;
    gemm_cm(wk, tid, sX, acc2);
#pragma unroll
    for (int j = 0; j < 8; ++j) {
        float2 v = upk(acc2[j]);
        g_Kf[(r0 + 2*j  )*DM_ + tid] = v.x;
        g_Kf[(r0 + 2*j+1)*DM_ + tid] = v.y;
        sKc[tid*PAD + 2*j]   = v.x;
        sKc[tid*PAD + 2*j+1] = v.y;
    }
    // v
#pragma unroll
    for (int j = 0; j < 8; ++j) acc2[j] = 0ull;
    gemm_cm(wv, tid, sX, acc2);
#pragma unroll
    for (int j = 0; j < 8; ++j) {
        float2 v = upk(acc2[j]);
        g_Vf[(r0 + 2*j  )*DM_ + tid] = v.x;
        g_Vf[(r0 + 2*j+1)*DM_ + tid] = v.y;
    }
    __syncthreads();

    // kn per row: 8 threads per row
    {
        int k = tid >> 3, lane = tid & 7;
        float k2 = 0.f;
#pragma unroll
        for (int i = 0; i < 16; ++i) {
            float v = sKc[(lane + 8*i)*PAD + k];
            k2 = fmaf(v, v, k2);
        }
#pragma unroll
        for (int off = 4; off; off >>= 1) k2 += __shfl_down_sync(0xffffffffu, k2, off, 8);
        if (lane == 0) g_kn[r0 + k] = fmaxf(sqrtf(k2), 1e-8f);
    }

    // QS2 = q @ SWG
#pragma unroll
    for (int j = 0; j < 8; ++j) acc2[j] = 0ull;
    gemm_cm(g_SWG, tid, sQc, acc2);
#pragma unroll
    for (int j = 0; j < 8; ++j) {
        float2 v = upk(acc2[j]);
        g_QS2[(r0 + 2*j  )*DM_ + tid] = v.x;
        g_QS2[(r0 + 2*j+1)*DM_ + tid] = v.y;
    }
    // KS2 = k @ SWG
#pragma unroll
    for (int j = 0; j < 8; ++j) acc2[j] = 0ull;
    gemm_cm(g_SWG, tid, sKc, acc2);
#pragma unroll
    for (int j = 0; j < 8; ++j) {
        float2 v = upk(acc2[j]);
        g_KS2[(r0 + 2*j  )*DM_ + tid] = v.x;
        g_KS2[(r0 + 2*j+1)*DM_ + tid] = v.y;
    }
}

// ---------------------------------------------------------------------------
// Kernel 3: stable top-16 KNN per query (matches stable argsort order).
// ---------------------------------------------------------------------------
__global__ __launch_bounds__(128) void knn_kernel(const float* __restrict__ xyz) {
    __shared__ float sx[N_];
    __shared__ float sy[N_];
    __shared__ float sz[N_];
    int b    = blockIdx.x >> 5;
    int qblk = blockIdx.x & 31;
    int tid  = threadIdx.x;
    const float* xb = xyz + (size_t)b * N_ * 3;
    for (int m = tid; m < N_; m += 128) {
        sx[m] = xb[m*3+0]; sy[m] = xb[m*3+1]; sz[m] = xb[m*3+2];
    }
    __syncthreads();

    int q = qblk * 128 + tid;
    float qx = sx[q], qy = sy[q], qz = sz[q];
    float qsq = qx*qx + qy*qy + qz*qz;

    float dist[16]; int idx[16];
#pragma unroll
    for (int i = 0; i < 16; ++i) { dist[i] = 3.4e38f; idx[i] = N_; }
    float worst = 3.4e38f;

    for (int m = 0; m < N_; ++m) {
        float mx = sx[m], my = sy[m], mz = sz[m];
        float msq = mx*mx + my*my + mz*mz;
        float dot = qx*mx + qy*my + qz*mz;
        float d   = qsq + msq - 2.0f*dot;
        if (d < worst) {
            float dd = d; int ii = m;
#pragma unroll
            for (int i = 0; i < 16; ++i) {
                if (dd < dist[i]) {
                    float td = dist[i]; dist[i] = dd; dd = td;
                    int   ti = idx[i];  idx[i]  = ii; ii = ti;
                }
            }
            worst = dist[15];
        }
    }
    int* op = g_idx + (size_t)(b*N_ + q) * K_;
#pragma unroll
    for (int i = 0; i < 16; ++i) op[i] = idx[i];
}

// ---------------------------------------------------------------------------
// Kernel 4: fused per-point block. One block = one point, thread = channel f.
// t = sim*u + QS2[n] - KS2[j] + relu(pe1)@Wp + cb ;  pos = relu(pe1)@d2 + d2b
// logits = relu(t)@g2 + g2b ; softmax(k) ; res = sum_k attn*(v+pos)
// ---------------------------------------------------------------------------
__global__ __launch_bounds__(128) void fused_kernel(
    const float* __restrict__ xyz,  const float* __restrict__ feat,
    const float* __restrict__ d1w,  const float* __restrict__ d1b,
    const float* __restrict__ d2w,  const float* __restrict__ d2b,
    const float* __restrict__ g2w,  const float* __restrict__ g2b,
    const float* __restrict__ fc2w, const float* __restrict__ fc2b,
    float* __restrict__ out_res,    float* __restrict__ out_attn)
{
    __shared__ __align__(16) float sCM[DM_*PAD];  // pe1, then h (col-major)
    __shared__ __align__(16) float sKr[16*DM_];   // gathered k rows
    __shared__ __align__(16) float sV [16*DM_];
    __shared__ float sQ[DM_];
    __shared__ float sRed[DM_];
    __shared__ float sSim[16];
    __shared__ float sKn[16];
    __shared__ float sRp[16][3];
    __shared__ int   sIdx[16];
    __shared__ float sQn;

    int tid = threadIdx.x;
    int p   = blockIdx.x;
    int b   = p >> 12;
    int base_b = b * N_;

    if (tid < 16) sIdx[tid] = g_idx[(size_t)p * K_ + tid];
    float qf   = g_Q  [(size_t)p * DM_ + tid];
    float QS2f = g_QS2[(size_t)p * DM_ + tid];
    float uf   = g_u[tid];
    float cbf  = g_cb[tid];
    sQ[tid] = qf;
    __syncthreads();                                   // S1

#pragma unroll
    for (int k = 0; k < 16; ++k) {
        int id = sIdx[k];
        size_t a = (size_t)(base_b + id) * DM_ + tid;
        sKr[k*DM_ + tid] = g_Kf[a];
        sV [k*DM_ + tid] = g_Vf[a];
    }
    if (tid < 16) {
        int id = sIdx[tid];
        const float* xp = xyz + (size_t)p * 3;
        const float* np = xyz + (size_t)(base_b + id) * 3;
        sRp[tid][0] = xp[0] - np[0];
        sRp[tid][1] = xp[1] - np[1];
        sRp[tid][2] = xp[2] - np[2];
        sKn[tid] = g_kn[base_b + id];
    }

    float v2 = qf * qf;
#pragma unroll
    for (int off = 16; off; off >>= 1) v2 += __shfl_down_sync(0xffffffffu, v2, off);
    if ((tid & 31) == 0) sRed[tid >> 5] = v2;
    __syncthreads();                                   // S2
    if (tid == 0) sQn = fmaxf(sqrtf(sRed[0] + sRed[1] + sRed[2] + sRed[3]), 1e-8f);

    // dot(q, k_j): 8 threads per neighbor
    {
        int k = tid >> 3, lane = tid & 7;
        float dp = 0.f;
#pragma unroll
        for (int i = 0; i < 16; ++i) {
            int f = lane + 8*i;
            dp = fmaf(sQ[f], sKr[k*DM_ + f], dp);
        }
#pragma unroll
        for (int off = 4; off; off >>= 1) dp += __shfl_down_sync(0xffffffffu, dp, off, 8);
        if (lane == 0) sSim[k] = dp;
    }
    __syncthreads();                                   // S3
    if (tid < 16) sSim[tid] = sSim[tid] / (sQn * sKn[tid]);

    // pe1 = relu(rel_pos @ d1 + b) into col-major sCM (thread owns column f)
    {
        float w0 = d1w[tid], w1 = d1w[DM_ + tid], w2 = d1w[2*DM_ + tid];
        float bb = d1b[tid];
#pragma unroll
        for (int k = 0; k < 16; ++k) {
            float vv = fmaf(sRp[k][0], w0, fmaf(sRp[k][1], w1, fmaf(sRp[k][2], w2, bb)));
            sCM[tid*PAD + k] = fmaxf(vv, 0.f);
        }
    }
    __syncthreads();                                   // S4

    // dual GEMM: pos += pe1@d2w ; t += pe1@Wp
    unsigned long long pos2[8], tac2[8];
    {
        float db   = d2b[tid];
        float base = QS2f + cbf;
#pragma unroll
        for (int j = 0; j < 8; ++j) {
            pos2[j] = pk(db, db);
            int k0 = 2*j;
            float t0 = fmaf(sSim[k0],   uf, base - g_KS2[(size_t)(base_b + sIdx[k0  ])*DM_ + tid]);
            float t1 = fmaf(sSim[k0+1], uf, base - g_KS2[(size_t)(base_b + sIdx[k0+1])*DM_ + tid]);
            tac2[j] = pk(t0, t1);
        }
    }
#pragma unroll 2
    for (int c = 0; c < DM_; ++c) {
        float wd = d2w[c*DM_ + tid];
        float wp = g_Wp[c*DM_ + tid];
        unsigned long long wd2 = pk(wd, wd), wp2 = pk(wp, wp);
        const ulonglong2* col = (const ulonglong2*)(sCM + c*PAD);
#pragma unroll
        for (int j = 0; j < 4; ++j) {
            ulonglong2 a = col[j];
            ffma2(pos2[2*j],   a.x, wd2);
            ffma2(pos2[2*j+1], a.y, wd2);
            ffma2(tac2[2*j],   a.x, wp2);
            ffma2(tac2[2*j+1], a.y, wp2);
        }
    }
    __syncthreads();                                   // S5: all done reading pe1

    // h = relu(t) into sCM (overwrite)
#pragma unroll
    for (int j = 0; j < 8; ++j) {
        float2 t = upk(tac2[j]);
        sCM[tid*PAD + 2*j]   = fmaxf(t.x, 0.f);
        sCM[tid*PAD + 2*j+1] = fmaxf(t.y, 0.f);
    }
    __syncthreads();                                   // S6

    // logits = h @ g2 + g2b
    unsigned long long lac2[8];
    {
        float gb = g2b[tid];
#pragma unroll
        for (int j = 0; j < 8; ++j) lac2[j] = pk(gb, gb);
    }
    gemm_cm(g2w, tid, sCM, lac2);

    // softmax over k (thread-local)
    float l[16], posv[16];
#pragma unroll
    for (int j = 0; j < 8; ++j) {
        float2 t = upk(lac2[j]);
        l[2*j] = t.x; l[2*j+1] = t.y;
        float2 pq = upk(pos2[j]);
        posv[2*j] = pq.x; posv[2*j+1] = pq.y;
    }
    const float scale = 1.0f / 11.313708498984760390f;
    float mxv = -3.4e38f;
#pragma unroll
    for (int k = 0; k < 16; ++k) { l[k] *= scale; mxv = fmaxf(mxv, l[k]); }
    float ssum = 0.f;
#pragma unroll
    for (int k = 0; k < 16; ++k) { l[k] = expf(l[k] - mxv); ssum += l[k]; }
    float inv = 1.0f / ssum;
    float resf = 0.f;
#pragma unroll
    for (int k = 0; k < 16; ++k) {
        float a = l[k] * inv;
        out_attn[((size_t)p * K_ + k) * DM_ + tid] = a;
        resf = fmaf(a, sV[k*DM_ + tid] + posv[k], resf);
    }
    sRed[tid] = resf;
    __syncthreads();                                   // S7

    if (tid < DP_) {
        float o = fc2b[tid] + feat[(size_t)p * DP_ + tid];
#pragma unroll 4
        for (int f = 0; f < DM_; ++f) o = fmaf(sRed[f], fc2w[f*DP_ + tid], o);
        out_res[(size_t)p * DP_ + tid] = o;
    }
}

// ---------------------------------------------------------------------------
extern "C" void kernel_launch(void* const* d_in, const int* in_sizes, int n_in,
                              void* d_out, int out_size) {
    const float* xyz   = (const float*)d_in[0];
    const float* feats = (const float*)d_in[1];
    const float* fc1w  = (const float*)d_in[2];
    const float* fc1b  = (const float*)d_in[3];
    const float* fc2w  = (const float*)d_in[4];
    const float* fc2b  = (const float*)d_in[5];
    const float* d1w   = (const float*)d_in[6];
    const float* d1b   = (const float*)d_in[7];
    const float* d2w   = (const float*)d_in[8];
    const float* d2b   = (const float*)d_in[9];
    const float* g1w   = (const float*)d_in[10];
    const float* g1b   = (const float*)d_in[11];
    const float* g2w   = (const float*)d_in[12];
    const float* g2b   = (const float*)d_in[13];
    const float* wqw   = (const float*)d_in[14];
    const float* wkw   = (const float*)d_in[15];
    const float* wvw   = (const float*)d_in[16];
    const float* simw  = (const float*)d_in[17];
    const float* simb  = (const float*)d_in[18];

    float* out      = (float*)d_out;
    float* out_res  = out;                       // (B, N, DP)
    float* out_attn = out + (size_t)B_*N_*DP_;   // (B, N, K, DM)

    wprep_kernel<<<DM_ + 1, 128>>>(d2w, d2b, g1w, g1b, simw, simb);
    fc1_kernel<<<NPTS/16, 128>>>(feats, fc1w, fc1b);
    qkv2_kernel<<<NPTS/16, 128>>>(wqw, wkw, wvw);
    knn_kernel<<<B_ * (N_/128), 128>>>(xyz);
    fused_kernel<<<NPTS, 128>>>(xyz, feats, d1w, d1b, d2w, d2b,
                                g2w, g2b, fc2w, fc2b, out_res, out_attn);
}

// round 9
// speedup vs baseline: 1.4525x; 1.0618x over previous
#include <cuda_runtime.h>
#include <math.h>

#define B_  4
#define N_  4096
#define K_  16
#define DP_ 64
#define DM_ 128
#define NPTS (B_*N_)
#define PAD 20   // col-major tile pad: 20 floats = 80B (16B aligned)
#define KNN_R 4          // candidate ranges per batch
#define KNN_RANGE (N_/KNN_R)   // 1024

// Scratch (device globals: no allocation allowed in kernel_launch)
__device__ float g_X  [NPTS*DM_];
__device__ float g_Q  [NPTS*DM_];
__device__ float g_Kf [NPTS*DM_];
__device__ float g_Vf [NPTS*DM_];
__device__ float g_QS2[NPTS*DM_];
__device__ float g_KS2[NPTS*DM_];
__device__ float g_kn [NPTS];
__device__ int   g_idx[NPTS*K_];
__device__ float g_pd [NPTS*KNN_R*K_];   // partial knn dists
__device__ int   g_pi [NPTS*KNN_R*K_];   // partial knn indices
__device__ float g_Wp [DM_*DM_];   // d2_w @ g1_w
__device__ float g_SWG[DM_*DM_];   // sim_w[1:] @ g1_w
__device__ float g_u  [DM_];       // sim_w[0] @ g1_w
__device__ float g_cb [DM_];       // (sim_b + d2_b) @ g1_w + g1_b

// ---------------------------------------------------------------------------
// fp32x2 packed helpers
// ---------------------------------------------------------------------------
__device__ __forceinline__ unsigned long long pk(float x, float y) {
    unsigned long long r;
    asm("mov.b64 %0, {%1, %2};" : "=l"(r) : "f"(x), "f"(y));
    return r;
}
__device__ __forceinline__ void ffma2(unsigned long long& d,
                                      unsigned long long a, unsigned long long b) {
    asm("fma.rn.f32x2 %0, %1, %2, %0;" : "+l"(d) : "l"(a), "l"(b));
}
__device__ __forceinline__ float2 upk(unsigned long long v) {
    float2 r;
    asm("mov.b64 {%0, %1}, %2;" : "=f"(r.x), "=f"(r.y) : "l"(v));
    return r;
}

// ---------------------------------------------------------------------------
// Col-major GEMM micro-kernel (see R6): thread = output column f.
// ---------------------------------------------------------------------------
__device__ __forceinline__ void gemm_cm(const float* __restrict__ W, int f,
                                        const float* sCM,
                                        unsigned long long acc2[8]) {
#pragma unroll 2
    for (int c = 0; c < DM_; ++c) {
        float w = W[c*DM_ + f];
        unsigned long long w2 = pk(w, w);
        const ulonglong2* col = (const ulonglong2*)(sCM + c*PAD);
#pragma unroll
        for (int j = 0; j < 4; ++j) {
            ulonglong2 a = col[j];
            ffma2(acc2[2*j],   a.x, w2);
            ffma2(acc2[2*j+1], a.y, w2);
        }
    }
}

// ---------------------------------------------------------------------------
// Kernel 0: fold weights
// ---------------------------------------------------------------------------
__global__ __launch_bounds__(128) void wprep_kernel(
    const float* __restrict__ d2w, const float* __restrict__ d2b,
    const float* __restrict__ g1w, const float* __restrict__ g1b,
    const float* __restrict__ simw, const float* __restrict__ simb)
{
    int f = threadIdx.x, i = blockIdx.x;
    if (i < DM_) {
        float a = 0.f, s = 0.f;
        for (int m = 0; m < DM_; ++m) {
            float g = g1w[m*DM_ + f];
            a = fmaf(d2w[i*DM_ + m], g, a);
            s = fmaf(simw[(1+i)*DM_ + m], g, s);
        }
        g_Wp[i*DM_ + f]  = a;
        g_SWG[i*DM_ + f] = s;
    } else {
        float u = 0.f, c = 0.f;
        for (int m = 0; m < DM_; ++m) {
            float g = g1w[m*DM_ + f];
            u = fmaf(simw[m], g, u);
            c = fmaf(simb[m] + d2b[m], g, c);
        }
        g_u[f]  = u;
        g_cb[f] = c + g1b[f];
    }
}

// ---------------------------------------------------------------------------
// Kernel 1: X = features @ fc1_w + fc1_b
// ---------------------------------------------------------------------------
__global__ __launch_bounds__(128) void fc1_kernel(const float* __restrict__ feat,
                                                  const float* __restrict__ W,
                                                  const float* __restrict__ bias) {
    __shared__ __align__(16) float sA[16*64];
    int tid = threadIdx.x;
    int r0  = blockIdx.x * 16;
    for (int i = tid; i < 16*64; i += 128) sA[i] = feat[r0*64 + i];
    __syncthreads();
    float acc[16];
    float bf = bias[tid];
#pragma unroll
    for (int k = 0; k < 16; ++k) acc[k] = bf;
#pragma unroll 2
    for (int kk = 0; kk < 16; ++kk) {
        float w0 = W[(kk*4+0)*DM_ + tid];
        float w1 = W[(kk*4+1)*DM_ + tid];
        float w2 = W[(kk*4+2)*DM_ + tid];
        float w3 = W[(kk*4+3)*DM_ + tid];
#pragma unroll
        for (int k = 0; k < 16; ++k) {
            float4 a = *(const float4*)&sA[k*64 + kk*4];
            acc[k] = fmaf(a.x, w0, acc[k]);
            acc[k] = fmaf(a.y, w1, acc[k]);
            acc[k] = fmaf(a.z, w2, acc[k]);
            acc[k] = fmaf(a.w, w3, acc[k]);
        }
    }
#pragma unroll
    for (int k = 0; k < 16; ++k) g_X[(r0 + k)*DM_ + tid] = acc[k];
}

// ---------------------------------------------------------------------------
// Kernel 2: q/k/v + QS2/KS2 + kn
// ---------------------------------------------------------------------------
__global__ __launch_bounds__(128) void qkv2_kernel(const float* __restrict__ wq,
                                                   const float* __restrict__ wk,
                                                   const float* __restrict__ wv) {
    __shared__ __align__(16) float sX [DM_*PAD];
    __shared__ __align__(16) float sQc[DM_*PAD];
    __shared__ __align__(16) float sKc[DM_*PAD];
    int tid = threadIdx.x;
    int r0  = blockIdx.x * 16;

    for (int i = tid; i < 16*DM_; i += 128) {
        int r = i >> 7, c = i & 127;
        sX[c*PAD + r] = g_X[r0*DM_ + i];
    }
    __syncthreads();

    unsigned long long acc2[8];
#pragma unroll
    for (int j = 0; j < 8; ++j) acc2[j] = 0ull;
    gemm_cm(wq, tid, sX, acc2);
#pragma unroll
    for (int j = 0; j < 8; ++j) {
        float2 v = upk(acc2[j]);
        g_Q[(r0 + 2*j  )*DM_ + tid] = v.x;
        g_Q[(r0 + 2*j+1)*DM_ + tid] = v.y;
        sQc[tid*PAD + 2*j]   = v.x;
        sQc[tid*PAD + 2*j+1] = v.y;
    }
#pragma unroll
    for (int j = 0; j < 8; ++j) acc2[j] = 0ull;
    gemm_cm(wk, tid, sX, acc2);
#pragma unroll
    for (int j = 0; j < 8; ++j) {
        float2 v = upk(acc2[j]);
        g_Kf[(r0 + 2*j  )*DM_ + tid] = v.x;
        g_Kf[(r0 + 2*j+1)*DM_ + tid] = v.y;
        sKc[tid*PAD + 2*j]   = v.x;
        sKc[tid*PAD + 2*j+1] = v.y;
    }
#pragma unroll
    for (int j = 0; j < 8; ++j) acc2[j] = 0ull;
    gemm_cm(wv, tid, sX, acc2);
#pragma unroll
    for (int j = 0; j < 8; ++j) {
        float2 v = upk(acc2[j]);
        g_Vf[(r0 + 2*j  )*DM_ + tid] = v.x;
        g_Vf[(r0 + 2*j+1)*DM_ + tid] = v.y;
    }
    __syncthreads();

    {
        int k = tid >> 3, lane = tid & 7;
        float k2 = 0.f;
#pragma unroll
        for (int i = 0; i < 16; ++i) {
            float v = sKc[(lane + 8*i)*PAD + k];
            k2 = fmaf(v, v, k2);
        }
#pragma unroll
        for (int off = 4; off; off >>= 1) k2 += __shfl_down_sync(0xffffffffu, k2, off, 8);
        if (lane == 0) g_kn[r0 + k] = fmaxf(sqrtf(k2), 1e-8f);
    }

#pragma unroll
    for (int j = 0; j < 8; ++j) acc2[j] = 0ull;
    gemm_cm(g_SWG, tid, sQc, acc2);
#pragma unroll
    for (int j = 0; j < 8; ++j) {
        float2 v = upk(acc2[j]);
        g_QS2[(r0 + 2*j  )*DM_ + tid] = v.x;
        g_QS2[(r0 + 2*j+1)*DM_ + tid] = v.y;
    }
#pragma unroll
    for (int j = 0; j < 8; ++j) acc2[j] = 0ull;
    gemm_cm(g_SWG, tid, sKc, acc2);
#pragma unroll
    for (int j = 0; j < 8; ++j) {
        float2 v = upk(acc2[j]);
        g_KS2[(r0 + 2*j  )*DM_ + tid] = v.x;
        g_KS2[(r0 + 2*j+1)*DM_ + tid] = v.y;
    }
}

// ---------------------------------------------------------------------------
// Kernel 3a: partial stable top-16 over a 1024-candidate range.
// grid = B * 32 qblocks * KNN_R ranges = 512 blocks of 128 threads.
// Candidates cached in smem as float4{x,y,z,|m|^2} (16 KB).
// ---------------------------------------------------------------------------
__global__ __launch_bounds__(128) void knn_part_kernel(const float* __restrict__ xyz) {
    __shared__ __align__(16) float4 sc[KNN_RANGE];
    int t    = blockIdx.x;
    int r    = t & (KNN_R - 1);
    int qblk = (t >> 2) & 31;
    int b    = t >> 7;
    int tid  = threadIdx.x;
    const float* xb = xyz + (size_t)b * N_ * 3;
    int m0 = r * KNN_RANGE;

    for (int m = tid; m < KNN_RANGE; m += 128) {
        float x = xb[(m0 + m)*3 + 0];
        float y = xb[(m0 + m)*3 + 1];
        float z = xb[(m0 + m)*3 + 2];
        sc[m] = make_float4(x, y, z, x*x + y*y + z*z);
    }
    __syncthreads();

    int q = qblk * 128 + tid;
    float qx = xb[q*3+0], qy = xb[q*3+1], qz = xb[q*3+2];
    float qsq = qx*qx + qy*qy + qz*qz;

    float dist[16]; int idx[16];
#pragma unroll
    for (int i = 0; i < 16; ++i) { dist[i] = 3.4e38f; idx[i] = 0x7fffffff; }
    float worst = 3.4e38f;

    for (int m = 0; m < KNN_RANGE; ++m) {
        float4 c = sc[m];
        float dot = qx*c.x + qy*c.y + qz*c.z;
        float d   = qsq + c.w - 2.0f*dot;
        if (d < worst) {
            float dd = d; int ii = m0 + m;
#pragma unroll
            for (int i = 0; i < 16; ++i) {
                if (dd < dist[i]) {
                    float td = dist[i]; dist[i] = dd; dd = td;
                    int   ti = idx[i];  idx[i]  = ii; ii = ti;
                }
            }
            worst = dist[15];
        }
    }
    float* pd = g_pd + ((size_t)(b*N_ + q) * KNN_R + r) * K_;
    int*   pi = g_pi + ((size_t)(b*N_ + q) * KNN_R + r) * K_;
#pragma unroll
    for (int i = 0; i < 16; ++i) { pd[i] = dist[i]; pi[i] = idx[i]; }
}

// ---------------------------------------------------------------------------
// Kernel 3b: 4-way merge of sorted partial lists -> stable top-16.
// Ties broken by smaller index == stable argsort order (ranges are
// ascending-index partitions, within-range lists already stable).
// ---------------------------------------------------------------------------
__global__ __launch_bounds__(128) void knn_merge_kernel() {
    int p = blockIdx.x * 128 + threadIdx.x;
    const float* pd = g_pd + (size_t)p * KNN_R * K_;
    const int*   pi = g_pi + (size_t)p * KNN_R * K_;
    int h[KNN_R];
#pragma unroll
    for (int r = 0; r < KNN_R; ++r) h[r] = 0;
    int* op = g_idx + (size_t)p * K_;
#pragma unroll
    for (int i = 0; i < 16; ++i) {
        float bd = 3.5e38f; int bi = 0x7fffffff; int br = 0;
#pragma unroll
        for (int r = 0; r < KNN_R; ++r) {
            if (h[r] < 16) {
                float d  = pd[r*K_ + h[r]];
                int   ix = pi[r*K_ + h[r]];
                if (d < bd || (d == bd && ix < bi)) { bd = d; bi = ix; br = r; }
            }
        }
        op[i] = bi;
        h[br]++;
    }
}

// ---------------------------------------------------------------------------
// Kernel 4: fused per-point block (unchanged from R6).
// ---------------------------------------------------------------------------
__global__ __launch_bounds__(128) void fused_kernel(
    const float* __restrict__ xyz,  const float* __restrict__ feat,
    const float* __restrict__ d1w,  const float* __restrict__ d1b,
    const float* __restrict__ d2w,  const float* __restrict__ d2b,
    const float* __restrict__ g2w,  const float* __restrict__ g2b,
    const float* __restrict__ fc2w, const float* __restrict__ fc2b,
    float* __restrict__ out_res,    float* __restrict__ out_attn)
{
    __shared__ __align__(16) float sCM[DM_*PAD];
    __shared__ __align__(16) float sKr[16*DM_];
    __shared__ __align__(16) float sV [16*DM_];
    __shared__ float sQ[DM_];
    __shared__ float sRed[DM_];
    __shared__ float sSim[16];
    __shared__ float sKn[16];
    __shared__ float sRp[16][3];
    __shared__ int   sIdx[16];
    __shared__ float sQn;

    int tid = threadIdx.x;
    int p   = blockIdx.x;
    int b   = p >> 12;
    int base_b = b * N_;

    if (tid < 16) sIdx[tid] = g_idx[(size_t)p * K_ + tid];
    float qf   = g_Q  [(size_t)p * DM_ + tid];
    float QS2f = g_QS2[(size_t)p * DM_ + tid];
    float uf   = g_u[tid];
    float cbf  = g_cb[tid];
    sQ[tid] = qf;
    __syncthreads();

#pragma unroll
    for (int k = 0; k < 16; ++k) {
        int id = sIdx[k];
        size_t a = (size_t)(base_b + id) * DM_ + tid;
        sKr[k*DM_ + tid] = g_Kf[a];
        sV [k*DM_ + tid] = g_Vf[a];
    }
    if (tid < 16) {
        int id = sIdx[tid];
        const float* xp = xyz + (size_t)p * 3;
        const float* np = xyz + (size_t)(base_b + id) * 3;
        sRp[tid][0] = xp[0] - np[0];
        sRp[tid][1] = xp[1] - np[1];
        sRp[tid][2] = xp[2] - np[2];
        sKn[tid] = g_kn[base_b + id];
    }

    float v2 = qf * qf;
#pragma unroll
    for (int off = 16; off; off >>= 1) v2 += __shfl_down_sync(0xffffffffu, v2, off);
    if ((tid & 31) == 0) sRed[tid >> 5] = v2;
    __syncthreads();
    if (tid == 0) sQn = fmaxf(sqrtf(sRed[0] + sRed[1] + sRed[2] + sRed[3]), 1e-8f);

    {
        int k = tid >> 3, lane = tid & 7;
        float dp = 0.f;
#pragma unroll
        for (int i = 0; i < 16; ++i) {
            int f = lane + 8*i;
            dp = fmaf(sQ[f], sKr[k*DM_ + f], dp);
        }
#pragma unroll
        for (int off = 4; off; off >>= 1) dp += __shfl_down_sync(0xffffffffu, dp, off, 8);
        if (lane == 0) sSim[k] = dp;
    }
    __syncthreads();
    if (tid < 16) sSim[tid] = sSim[tid] / (sQn * sKn[tid]);

    {
        float w0 = d1w[tid], w1 = d1w[DM_ + tid], w2 = d1w[2*DM_ + tid];
        float bb = d1b[tid];
#pragma unroll
        for (int k = 0; k < 16; ++k) {
            float vv = fmaf(sRp[k][0], w0, fmaf(sRp[k][1], w1, fmaf(sRp[k][2], w2, bb)));
            sCM[tid*PAD + k] = fmaxf(vv, 0.f);
        }
    }
    __syncthreads();

    unsigned long long pos2[8], tac2[8];
    {
        float db   = d2b[tid];
        float base = QS2f + cbf;
#pragma unroll
        for (int j = 0; j < 8; ++j) {
            pos2[j] = pk(db, db);
            int k0 = 2*j;
            float t0 = fmaf(sSim[k0],   uf, base - g_KS2[(size_t)(base_b + sIdx[k0  ])*DM_ + tid]);
            float t1 = fmaf(sSim[k0+1], uf, base - g_KS2[(size_t)(base_b + sIdx[k0+1])*DM_ + tid]);
            tac2[j] = pk(t0, t1);
        }
    }
#pragma unroll 2
    for (int c = 0; c < DM_; ++c) {
        float wd = d2w[c*DM_ + tid];
        float wp = g_Wp[c*DM_ + tid];
        unsigned long long wd2 = pk(wd, wd), wp2 = pk(wp, wp);
        const ulonglong2* col = (const ulonglong2*)(sCM + c*PAD);
#pragma unroll
        for (int j = 0; j < 4; ++j) {
            ulonglong2 a = col[j];
            ffma2(pos2[2*j],   a.x, wd2);
            ffma2(pos2[2*j+1], a.y, wd2);
            ffma2(tac2[2*j],   a.x, wp2);
            ffma2(tac2[2*j+1], a.y, wp2);
        }
    }
    __syncthreads();

#pragma unroll
    for (int j = 0; j < 8; ++j) {
        float2 t = upk(tac2[j]);
        sCM[tid*PAD + 2*j]   = fmaxf(t.x, 0.f);
        sCM[tid*PAD + 2*j+1] = fmaxf(t.y, 0.f);
    }
    __syncthreads();

    unsigned long long lac2[8];
    {
        float gb = g2b[tid];
#pragma unroll
        for (int j = 0; j < 8; ++j) lac2[j] = pk(gb, gb);
    }
    gemm_cm(g2w, tid, sCM, lac2);

    float l[16], posv[16];
#pragma unroll
    for (int j = 0; j < 8; ++j) {
        float2 t = upk(lac2[j]);
        l[2*j] = t.x; l[2*j+1] = t.y;
        float2 pq = upk(pos2[j]);
        posv[2*j] = pq.x; posv[2*j+1] = pq.y;
    }
    const float scale = 1.0f / 11.313708498984760390f;
    float mxv = -3.4e38f;
#pragma unroll
    for (int k = 0; k < 16; ++k) { l[k] *= scale; mxv = fmaxf(mxv, l[k]); }
    float ssum = 0.f;
#pragma unroll
    for (int k = 0; k < 16; ++k) { l[k] = expf(l[k] - mxv); ssum += l[k]; }
    float inv = 1.0f / ssum;
    float resf = 0.f;
#pragma unroll
    for (int k = 0; k < 16; ++k) {
        float a = l[k] * inv;
        out_attn[((size_t)p * K_ + k) * DM_ + tid] = a;
        resf = fmaf(a, sV[k*DM_ + tid] + posv[k], resf);
    }
    sRed[tid] = resf;
    __syncthreads();

    if (tid < DP_) {
        float o = fc2b[tid] + feat[(size_t)p * DP_ + tid];
#pragma unroll 4
        for (int f = 0; f < DM_; ++f) o = fmaf(sRed[f], fc2w[f*DP_ + tid], o);
        out_res[(size_t)p * DP_ + tid] = o;
    }
}

// ---------------------------------------------------------------------------
extern "C" void kernel_launch(void* const* d_in, const int* in_sizes, int n_in,
                              void* d_out, int out_size) {
    const float* xyz   = (const float*)d_in[0];
    const float* feats = (const float*)d_in[1];
    const float* fc1w  = (const float*)d_in[2];
    const float* fc1b  = (const float*)d_in[3];
    const float* fc2w  = (const float*)d_in[4];
    const float* fc2b  = (const float*)d_in[5];
    const float* d1w   = (const float*)d_in[6];
    const float* d1b   = (const float*)d_in[7];
    const float* d2w   = (const float*)d_in[8];
    const float* d2b   = (const float*)d_in[9];
    const float* g1w   = (const float*)d_in[10];
    const float* g1b   = (const float*)d_in[11];
    const float* g2w   = (const float*)d_in[12];
    const float* g2b   = (const float*)d_in[13];
    const float* wqw   = (const float*)d_in[14];
    const float* wkw   = (const float*)d_in[15];
    const float* wvw   = (const float*)d_in[16];
    const float* simw  = (const float*)d_in[17];
    const float* simb  = (const float*)d_in[18];

    float* out      = (float*)d_out;
    float* out_res  = out;                       // (B, N, DP)
    float* out_attn = out + (size_t)B_*N_*DP_;   // (B, N, K, DM)

    wprep_kernel<<<DM_ + 1, 128>>>(d2w, d2b, g1w, g1b, simw, simb);
    fc1_kernel<<<NPTS/16, 128>>>(feats, fc1w, fc1b);
    qkv2_kernel<<<NPTS/16, 128>>>(wqw, wkw, wvw);
    knn_part_kernel<<<B_ * 32 * KNN_R, 128>>>(xyz);
    knn_merge_kernel<<<NPTS/128, 128>>>();
    fused_kernel<<<NPTS, 128>>>(xyz, feats, d1w, d1b, d2w, d2b,
                                g2w, g2b, fc2w, fc2b, out_res, out_attn);
}

// round 10
// speedup vs baseline: 1.7758x; 1.2225x over previous
#include <cuda_runtime.h>
#include <math.h>

#define B_  4
#define N_  4096
#define K_  16
#define DP_ 64
#define DM_ 128
#define NPTS (B_*N_)
#define PAD 20   // col-major tile pad: 20 floats = 80B (16B aligned)

// Scratch (device globals: no allocation allowed in kernel_launch)
__device__ float g_X  [NPTS*DM_];
__device__ float g_Q  [NPTS*DM_];
__device__ float g_Kf [NPTS*DM_];
__device__ float g_Vf [NPTS*DM_];
__device__ float g_QS2[NPTS*DM_];
__device__ float g_KS2[NPTS*DM_];
__device__ float g_kn [NPTS];
__device__ int   g_idx[NPTS*K_];
__device__ float g_Wp [DM_*DM_];   // d2_w @ g1_w
__device__ float g_SWG[DM_*DM_];   // sim_w[1:] @ g1_w
__device__ float g_u  [DM_];       // sim_w[0] @ g1_w
__device__ float g_cb [DM_];       // (sim_b + d2_b) @ g1_w + g1_b

// ---------------------------------------------------------------------------
// fp32x2 packed helpers
// ---------------------------------------------------------------------------
__device__ __forceinline__ unsigned long long pk(float x, float y) {
    unsigned long long r;
    asm("mov.b64 %0, {%1, %2};" : "=l"(r) : "f"(x), "f"(y));
    return r;
}
__device__ __forceinline__ void ffma2(unsigned long long& d,
                                      unsigned long long a, unsigned long long b) {
    asm("fma.rn.f32x2 %0, %1, %2, %0;" : "+l"(d) : "l"(a), "l"(b));
}
__device__ __forceinline__ float2 upk(unsigned long long v) {
    float2 r;
    asm("mov.b64 {%0, %1}, %2;" : "=f"(r.x), "=f"(r.y) : "l"(v));
    return r;
}

// ---------------------------------------------------------------------------
// Col-major GEMM micro-kernel: thread = output column f.
// ---------------------------------------------------------------------------
__device__ __forceinline__ void gemm_cm(const float* __restrict__ W, int f,
                                        const float* sCM,
                                        unsigned long long acc2[8]) {
#pragma unroll 2
    for (int c = 0; c < DM_; ++c) {
        float w = W[c*DM_ + f];
        unsigned long long w2 = pk(w, w);
        const ulonglong2* col = (const ulonglong2*)(sCM + c*PAD);
#pragma unroll
        for (int j = 0; j < 4; ++j) {
            ulonglong2 a = col[j];
            ffma2(acc2[2*j],   a.x, w2);
            ffma2(acc2[2*j+1], a.y, w2);
        }
    }
}

// ---------------------------------------------------------------------------
// Kernel 0: fold weights
// ---------------------------------------------------------------------------
__global__ __launch_bounds__(128) void wprep_kernel(
    const float* __restrict__ d2w, const float* __restrict__ d2b,
    const float* __restrict__ g1w, const float* __restrict__ g1b,
    const float* __restrict__ simw, const float* __restrict__ simb)
{
    int f = threadIdx.x, i = blockIdx.x;
    if (i < DM_) {
        float a = 0.f, s = 0.f;
        for (int m = 0; m < DM_; ++m) {
            float g = g1w[m*DM_ + f];
            a = fmaf(d2w[i*DM_ + m], g, a);
            s = fmaf(simw[(1+i)*DM_ + m], g, s);
        }
        g_Wp[i*DM_ + f]  = a;
        g_SWG[i*DM_ + f] = s;
    } else {
        float u = 0.f, c = 0.f;
        for (int m = 0; m < DM_; ++m) {
            float g = g1w[m*DM_ + f];
            u = fmaf(simw[m], g, u);
            c = fmaf(simb[m] + d2b[m], g, c);
        }
        g_u[f]  = u;
        g_cb[f] = c + g1b[f];
    }
}

// ---------------------------------------------------------------------------
// Kernel 1: X = features @ fc1_w + fc1_b
// ---------------------------------------------------------------------------
__global__ __launch_bounds__(128) void fc1_kernel(const float* __restrict__ feat,
                                                  const float* __restrict__ W,
                                                  const float* __restrict__ bias) {
    __shared__ __align__(16) float sA[16*64];
    int tid = threadIdx.x;
    int r0  = blockIdx.x * 16;
    for (int i = tid; i < 16*64; i += 128) sA[i] = feat[r0*64 + i];
    __syncthreads();
    float acc[16];
    float bf = bias[tid];
#pragma unroll
    for (int k = 0; k < 16; ++k) acc[k] = bf;
#pragma unroll 2
    for (int kk = 0; kk < 16; ++kk) {
        float w0 = W[(kk*4+0)*DM_ + tid];
        float w1 = W[(kk*4+1)*DM_ + tid];
        float w2 = W[(kk*4+2)*DM_ + tid];
        float w3 = W[(kk*4+3)*DM_ + tid];
#pragma unroll
        for (int k = 0; k < 16; ++k) {
            float4 a = *(const float4*)&sA[k*64 + kk*4];
            acc[k] = fmaf(a.x, w0, acc[k]);
            acc[k] = fmaf(a.y, w1, acc[k]);
            acc[k] = fmaf(a.z, w2, acc[k]);
            acc[k] = fmaf(a.w, w3, acc[k]);
        }
    }
#pragma unroll
    for (int k = 0; k < 16; ++k) g_X[(r0 + k)*DM_ + tid] = acc[k];
}

// ---------------------------------------------------------------------------
// Kernel 2: q/k/v + QS2/KS2 + kn
// ---------------------------------------------------------------------------
__global__ __launch_bounds__(128) void qkv2_kernel(const float* __restrict__ wq,
                                                   const float* __restrict__ wk,
                                                   const float* __restrict__ wv) {
    __shared__ __align__(16) float sX [DM_*PAD];
    __shared__ __align__(16) float sQc[DM_*PAD];
    __shared__ __align__(16) float sKc[DM_*PAD];
    int tid = threadIdx.x;
    int r0  = blockIdx.x * 16;

    for (int i = tid; i < 16*DM_; i += 128) {
        int r = i >> 7, c = i & 127;
        sX[c*PAD + r] = g_X[r0*DM_ + i];
    }
    __syncthreads();

    unsigned long long acc2[8];
#pragma unroll
    for (int j = 0; j < 8; ++j) acc2[j] = 0ull;
    gemm_cm(wq, tid, sX, acc2);
#pragma unroll
    for (int j = 0; j < 8; ++j) {
        float2 v = upk(acc2[j]);
        g_Q[(r0 + 2*j  )*DM_ + tid] = v.x;
        g_Q[(r0 + 2*j+1)*DM_ + tid] = v.y;
        sQc[tid*PAD + 2*j]   = v.x;
        sQc[tid*PAD + 2*j+1] = v.y;
    }
#pragma unroll
    for (int j = 0; j < 8; ++j) acc2[j] = 0ull;
    gemm_cm(wk, tid, sX, acc2);
#pragma unroll
    for (int j = 0; j < 8; ++j) {
        float2 v = upk(acc2[j]);
        g_Kf[(r0 + 2*j  )*DM_ + tid] = v.x;
        g_Kf[(r0 + 2*j+1)*DM_ + tid] = v.y;
        sKc[tid*PAD + 2*j]   = v.x;
        sKc[tid*PAD + 2*j+1] = v.y;
    }
#pragma unroll
    for (int j = 0; j < 8; ++j) acc2[j] = 0ull;
    gemm_cm(wv, tid, sX, acc2);
#pragma unroll
    for (int j = 0; j < 8; ++j) {
        float2 v = upk(acc2[j]);
        g_Vf[(r0 + 2*j  )*DM_ + tid] = v.x;
        g_Vf[(r0 + 2*j+1)*DM_ + tid] = v.y;
    }
    __syncthreads();

    {
        int k = tid >> 3, lane = tid & 7;
        float k2 = 0.f;
#pragma unroll
        for (int i = 0; i < 16; ++i) {
            float v = sKc[(lane + 8*i)*PAD + k];
            k2 = fmaf(v, v, k2);
        }
#pragma unroll
        for (int off = 4; off; off >>= 1) k2 += __shfl_down_sync(0xffffffffu, k2, off, 8);
        if (lane == 0) g_kn[r0 + k] = fmaxf(sqrtf(k2), 1e-8f);
    }

#pragma unroll
    for (int j = 0; j < 8; ++j) acc2[j] = 0ull;
    gemm_cm(g_SWG, tid, sQc, acc2);
#pragma unroll
    for (int j = 0; j < 8; ++j) {
        float2 v = upk(acc2[j]);
        g_QS2[(r0 + 2*j  )*DM_ + tid] = v.x;
        g_QS2[(r0 + 2*j+1)*DM_ + tid] = v.y;
    }
#pragma unroll
    for (int j = 0; j < 8; ++j) acc2[j] = 0ull;
    gemm_cm(g_SWG, tid, sKc, acc2);
#pragma unroll
    for (int j = 0; j < 8; ++j) {
        float2 v = upk(acc2[j]);
        g_KS2[(r0 + 2*j  )*DM_ + tid] = v.x;
        g_KS2[(r0 + 2*j+1)*DM_ + tid] = v.y;
    }
}

// ---------------------------------------------------------------------------
// Kernel 3: warp-per-query stable top-16 KNN over the full batch.
// Top-16 list is lane-distributed (lane l of the warp holds the l-th
// smallest packed key (orderable(dist)<<32 | idx)). Per 32-candidate step:
// one ballot vs threshold tau = list[15]; rare inserts are O(1) warp-coop:
// pos = popc(ballot(cur < c)), shfl_up shift, select.
// Packed (dist, idx) lexicographic order == stable argsort order.
// ---------------------------------------------------------------------------
#define KNN_WARPS 8
__global__ __launch_bounds__(32*KNN_WARPS) void knn_warp_kernel(const float* __restrict__ xyz) {
    __shared__ float sx[N_];
    __shared__ float sy[N_];
    __shared__ float sz[N_];
    int tid  = threadIdx.x;
    int warp = tid >> 5, lane = tid & 31;
    int blkPerBatch = N_ / KNN_WARPS;          // 512
    int b = blockIdx.x / blkPerBatch;
    int q = (blockIdx.x % blkPerBatch) * KNN_WARPS + warp;
    const float* xb = xyz + (size_t)b * N_ * 3;

    for (int m = tid; m < N_; m += 32*KNN_WARPS) {
        sx[m] = xb[m*3+0]; sy[m] = xb[m*3+1]; sz[m] = xb[m*3+2];
    }
    __syncthreads();

    float qx = sx[q], qy = sy[q], qz = sz[q];
    float qsq = qx*qx + qy*qy + qz*qz;

    unsigned long long cur = ~0ull;     // lane-distributed sorted list (lanes 0..15)
    unsigned long long tau = ~0ull;     // current 16th-best key

#pragma unroll 4
    for (int s = 0; s < N_/32; ++s) {
        int m = s*32 + lane;
        float mx = sx[m], my = sy[m], mz = sz[m];
        float msq = mx*mx + my*my + mz*mz;
        float dot = qx*mx + qy*my + qz*mz;
        float d   = qsq + msq - 2.0f*dot;
        // monotonic float->uint fold (handles tiny negative d)
        unsigned ub = __float_as_uint(d);
        ub ^= (unsigned)((int)ub >> 31) | 0x80000000u;
        unsigned long long key = ((unsigned long long)ub << 32) | (unsigned)m;

        unsigned ballot = __ballot_sync(0xffffffffu, key < tau);
        while (ballot) {                       // uniform loop
            int src = __ffs(ballot) - 1;
            ballot &= ballot - 1;
            unsigned long long cb = __shfl_sync(0xffffffffu, key, src);
            if (cb >= tau) continue;           // tau tightened; uniform branch
            unsigned less = __ballot_sync(0xffffffffu, cur < cb) & 0xffffu;
            int pos = __popc(less);            // <= 15 since cb < cur[15]
            unsigned long long sh = __shfl_up_sync(0xffffffffu, cur, 1);
            if (lane > pos) cur = sh;
            else if (lane == pos) cur = cb;
            tau = __shfl_sync(0xffffffffu, cur, 15);
        }
    }
    if (lane < 16) g_idx[(size_t)(b*N_ + q) * K_ + lane] = (int)(unsigned)cur;
}

// ---------------------------------------------------------------------------
// Kernel 4: fused per-point block (unchanged).
// ---------------------------------------------------------------------------
__global__ __launch_bounds__(128) void fused_kernel(
    const float* __restrict__ xyz,  const float* __restrict__ feat,
    const float* __restrict__ d1w,  const float* __restrict__ d1b,
    const float* __restrict__ d2w,  const float* __restrict__ d2b,
    const float* __restrict__ g2w,  const float* __restrict__ g2b,
    const float* __restrict__ fc2w, const float* __restrict__ fc2b,
    float* __restrict__ out_res,    float* __restrict__ out_attn)
{
    __shared__ __align__(16) float sCM[DM_*PAD];
    __shared__ __align__(16) float sKr[16*DM_];
    __shared__ __align__(16) float sV [16*DM_];
    __shared__ float sQ[DM_];
    __shared__ float sRed[DM_];
    __shared__ float sSim[16];
    __shared__ float sKn[16];
    __shared__ float sRp[16][3];
    __shared__ int   sIdx[16];
    __shared__ float sQn;

    int tid = threadIdx.x;
    int p   = blockIdx.x;
    int b   = p >> 12;
    int base_b = b * N_;

    if (tid < 16) sIdx[tid] = g_idx[(size_t)p * K_ + tid];
    float qf   = g_Q  [(size_t)p * DM_ + tid];
    float QS2f = g_QS2[(size_t)p * DM_ + tid];
    float uf   = g_u[tid];
    float cbf  = g_cb[tid];
    sQ[tid] = qf;
    __syncthreads();

#pragma unroll
    for (int k = 0; k < 16; ++k) {
        int id = sIdx[k];
        size_t a = (size_t)(base_b + id) * DM_ + tid;
        sKr[k*DM_ + tid] = g_Kf[a];
        sV [k*DM_ + tid] = g_Vf[a];
    }
    if (tid < 16) {
        int id = sIdx[tid];
        const float* xp = xyz + (size_t)p * 3;
        const float* np = xyz + (size_t)(base_b + id) * 3;
        sRp[tid][0] = xp[0] - np[0];
        sRp[tid][1] = xp[1] - np[1];
        sRp[tid][2] = xp[2] - np[2];
        sKn[tid] = g_kn[base_b + id];
    }

    float v2 = qf * qf;
#pragma unroll
    for (int off = 16; off; off >>= 1) v2 += __shfl_down_sync(0xffffffffu, v2, off);
    if ((tid & 31) == 0) sRed[tid >> 5] = v2;
    __syncthreads();
    if (tid == 0) sQn = fmaxf(sqrtf(sRed[0] + sRed[1] + sRed[2] + sRed[3]), 1e-8f);

    {
        int k = tid >> 3, lane = tid & 7;
        float dp = 0.f;
#pragma unroll
        for (int i = 0; i < 16; ++i) {
            int f = lane + 8*i;
            dp = fmaf(sQ[f], sKr[k*DM_ + f], dp);
        }
#pragma unroll
        for (int off = 4; off; off >>= 1) dp += __shfl_down_sync(0xffffffffu, dp, off, 8);
        if (lane == 0) sSim[k] = dp;
    }
    __syncthreads();
    if (tid < 16) sSim[tid] = sSim[tid] / (sQn * sKn[tid]);

    {
        float w0 = d1w[tid], w1 = d1w[DM_ + tid], w2 = d1w[2*DM_ + tid];
        float bb = d1b[tid];
#pragma unroll
        for (int k = 0; k < 16; ++k) {
            float vv = fmaf(sRp[k][0], w0, fmaf(sRp[k][1], w1, fmaf(sRp[k][2], w2, bb)));
            sCM[tid*PAD + k] = fmaxf(vv, 0.f);
        }
    }
    __syncthreads();

    unsigned long long pos2[8], tac2[8];
    {
        float db   = d2b[tid];
        float base = QS2f + cbf;
#pragma unroll
        for (int j = 0; j < 8; ++j) {
            pos2[j] = pk(db, db);
            int k0 = 2*j;
            float t0 = fmaf(sSim[k0],   uf, base - g_KS2[(size_t)(base_b + sIdx[k0  ])*DM_ + tid]);
            float t1 = fmaf(sSim[k0+1], uf, base - g_KS2[(size_t)(base_b + sIdx[k0+1])*DM_ + tid]);
            tac2[j] = pk(t0, t1);
        }
    }
#pragma unroll 2
    for (int c = 0; c < DM_; ++c) {
        float wd = d2w[c*DM_ + tid];
        float wp = g_Wp[c*DM_ + tid];
        unsigned long long wd2 = pk(wd, wd), wp2 = pk(wp, wp);
        const ulonglong2* col = (const ulonglong2*)(sCM + c*PAD);
#pragma unroll
        for (int j = 0; j < 4; ++j) {
            ulonglong2 a = col[j];
            ffma2(pos2[2*j],   a.x, wd2);
            ffma2(pos2[2*j+1], a.y, wd2);
            ffma2(tac2[2*j],   a.x, wp2);
            ffma2(tac2[2*j+1], a.y, wp2);
        }
    }
    __syncthreads();

#pragma unroll
    for (int j = 0; j < 8; ++j) {
        float2 t = upk(tac2[j]);
        sCM[tid*PAD + 2*j]   = fmaxf(t.x, 0.f);
        sCM[tid*PAD + 2*j+1] = fmaxf(t.y, 0.f);
    }
    __syncthreads();

    unsigned long long lac2[8];
    {
        float gb = g2b[tid];
#pragma unroll
        for (int j = 0; j < 8; ++j) lac2[j] = pk(gb, gb);
    }
    gemm_cm(g2w, tid, sCM, lac2);

    float l[16], posv[16];
#pragma unroll
    for (int j = 0; j < 8; ++j) {
        float2 t = upk(lac2[j]);
        l[2*j] = t.x; l[2*j+1] = t.y;
        float2 pq = upk(pos2[j]);
        posv[2*j] = pq.x; posv[2*j+1] = pq.y;
    }
    const float scale = 1.0f / 11.313708498984760390f;
    float mxv = -3.4e38f;
#pragma unroll
    for (int k = 0; k < 16; ++k) { l[k] *= scale; mxv = fmaxf(mxv, l[k]); }
    float ssum = 0.f;
#pragma unroll
    for (int k = 0; k < 16; ++k) { l[k] = expf(l[k] - mxv); ssum += l[k]; }
    float inv = 1.0f / ssum;
    float resf = 0.f;
#pragma unroll
    for (int k = 0; k < 16; ++k) {
        float a = l[k] * inv;
        out_attn[((size_t)p * K_ + k) * DM_ + tid] = a;
        resf = fmaf(a, sV[k*DM_ + tid] + posv[k], resf);
    }
    sRed[tid] = resf;
    __syncthreads();

    if (tid < DP_) {
        float o = fc2b[tid] + feat[(size_t)p * DP_ + tid];
#pragma unroll 4
        for (int f = 0; f < DM_; ++f) o = fmaf(sRed[f], fc2w[f*DP_ + tid], o);
        out_res[(size_t)p * DP_ + tid] = o;
    }
}

// ---------------------------------------------------------------------------
extern "C" void kernel_launch(void* const* d_in, const int* in_sizes, int n_in,
                              void* d_out, int out_size) {
    const float* xyz   = (const float*)d_in[0];
    const float* feats = (const float*)d_in[1];
    const float* fc1w  = (const float*)d_in[2];
    const float* fc1b  = (const float*)d_in[3];
    const float* fc2w  = (const float*)d_in[4];
    const float* fc2b  = (const float*)d_in[5];
    const float* d1w   = (const float*)d_in[6];
    const float* d1b   = (const float*)d_in[7];
    const float* d2w   = (const float*)d_in[8];
    const float* d2b   = (const float*)d_in[9];
    const float* g1w   = (const float*)d_in[10];
    const float* g1b   = (const float*)d_in[11];
    const float* g2w   = (const float*)d_in[12];
    const float* g2b   = (const float*)d_in[13];
    const float* wqw   = (const float*)d_in[14];
    const float* wkw   = (const float*)d_in[15];
    const float* wvw   = (const float*)d_in[16];
    const float* simw  = (const float*)d_in[17];
    const float* simb  = (const float*)d_in[18];

    float* out      = (float*)d_out;
    float* out_res  = out;                       // (B, N, DP)
    float* out_attn = out + (size_t)B_*N_*DP_;   // (B, N, K, DM)

    wprep_kernel<<<DM_ + 1, 128>>>(d2w, d2b, g1w, g1b, simw, simb);
    fc1_kernel<<<NPTS/16, 128>>>(feats, fc1w, fc1b);
    qkv2_kernel<<<NPTS/16, 128>>>(wqw, wkw, wvw);
    knn_warp_kernel<<<B_ * (N_/KNN_WARPS), 32*KNN_WARPS>>>(xyz);
    fused_kernel<<<NPTS, 128>>>(xyz, feats, d1w, d1b, d2w, d2b,
                                g2w, g2b, fc2w, fc2b, out_res, out_attn);
}

// round 13
// speedup vs baseline: 2.0516x; 1.1554x over previous
#include <cuda_runtime.h>
#include <math.h>

#define B_  4
#define N_  4096
#define K_  16
#define DP_ 64
#define DM_ 128
#define NPTS (B_*N_)
#define PAD 20   // col-major tile pad: 20 floats = 80B (16B aligned)

// Scratch (device globals: no allocation allowed in kernel_launch)
__device__ float g_Q  [NPTS*DM_];
__device__ float g_Kf [NPTS*DM_];
__device__ float g_Vf [NPTS*DM_];
__device__ float g_QS2[NPTS*DM_];
__device__ float g_KS2[NPTS*DM_];
__device__ float g_kn [NPTS];
__device__ int   g_idx[NPTS*K_];
__device__ float g_Wp [DM_*DM_];   // d2_w @ g1_w
__device__ float g_SWG[DM_*DM_];   // sim_w[1:] @ g1_w
__device__ float g_u  [DM_];       // sim_w[0] @ g1_w
__device__ float g_cb [DM_];       // (sim_b + d2_b) @ g1_w + g1_b
// folded projection weights (K=64)
__device__ float g_Wq2[DP_*DM_];   // fc1w @ wq
__device__ float g_Wk2[DP_*DM_];   // fc1w @ wk
__device__ float g_Wv2[DP_*DM_];   // fc1w @ wv
__device__ float g_Wqs[DP_*DM_];   // fc1w @ wq @ SWG
__device__ float g_Wks[DP_*DM_];   // fc1w @ wk @ SWG
__device__ float g_bq [DM_];       // fc1b @ wq
__device__ float g_bk [DM_];
__device__ float g_bv [DM_];
__device__ float g_bqs[DM_];       // bq @ SWG
__device__ float g_bks[DM_];

// ---------------------------------------------------------------------------
// fp32x2 packed helpers
// ---------------------------------------------------------------------------
__device__ __forceinline__ unsigned long long pk(float x, float y) {
    unsigned long long r;
    asm("mov.b64 %0, {%1, %2};" : "=l"(r) : "f"(x), "f"(y));
    return r;
}
__device__ __forceinline__ void ffma2(unsigned long long& d,
                                      unsigned long long a, unsigned long long b) {
    asm("fma.rn.f32x2 %0, %1, %2, %0;" : "+l"(d) : "l"(a), "l"(b));
}
__device__ __forceinline__ float2 upk(unsigned long long v) {
    float2 r;
    asm("mov.b64 {%0, %1}, %2;" : "=f"(r.x), "=f"(r.y) : "l"(v));
    return r;
}

// ---------------------------------------------------------------------------
// Col-major GEMM micro-kernel: A is 16 rows x KD cols col-major
// (column c at sCM[c*PAD .. +15]). Thread = output column f.
// ---------------------------------------------------------------------------
template<int KD>
__device__ __forceinline__ void gemm_cm_t(const float* __restrict__ W, int f,
                                          const float* sCM,
                                          unsigned long long acc2[8]) {
#pragma unroll 4
    for (int c = 0; c < KD; ++c) {
        float w = W[c*DM_ + f];
        unsigned long long w2 = pk(w, w);
        const ulonglong2* col = (const ulonglong2*)(sCM + c*PAD);
#pragma unroll
        for (int j = 0; j < 4; ++j) {
            ulonglong2 a = col[j];
            ffma2(acc2[2*j],   a.x, w2);
            ffma2(acc2[2*j+1], a.y, w2);
        }
    }
}

// ---------------------------------------------------------------------------
// Kernel 0a: SWG = sim_w[1:]@g1w, Wp = d2w@g1w, u = sim_w[0]@g1w,
//            cb = (sim_b+d2_b)@g1w + g1b
// ---------------------------------------------------------------------------
__global__ __launch_bounds__(128) void wprep1_kernel(
    const float* __restrict__ d2w, const float* __restrict__ d2b,
    const float* __restrict__ g1w, const float* __restrict__ g1b,
    const float* __restrict__ simw, const float* __restrict__ simb)
{
    int f = threadIdx.x, i = blockIdx.x;
    if (i < DM_) {
        float a = 0.f, s = 0.f;
        for (int m = 0; m < DM_; ++m) {
            float g = g1w[m*DM_ + f];
            a = fmaf(d2w[i*DM_ + m], g, a);
            s = fmaf(simw[(1+i)*DM_ + m], g, s);
        }
        g_Wp[i*DM_ + f]  = a;
        g_SWG[i*DM_ + f] = s;
    } else {
        float u = 0.f, c = 0.f;
        for (int m = 0; m < DM_; ++m) {
            float g = g1w[m*DM_ + f];
            u = fmaf(simw[m], g, u);
            c = fmaf(simb[m] + d2b[m], g, c);
        }
        g_u[f]  = u;
        g_cb[f] = c + g1b[f];
    }
}

// ---------------------------------------------------------------------------
// Kernel 0b: Wq2 = fc1w@wq, Wk2 = fc1w@wk, Wv2 = fc1w@wv (+ biases)
// ---------------------------------------------------------------------------
__global__ __launch_bounds__(128) void wprep2_kernel(
    const float* __restrict__ fc1w, const float* __restrict__ fc1b,
    const float* __restrict__ wq, const float* __restrict__ wk,
    const float* __restrict__ wv)
{
    int f = threadIdx.x, i = blockIdx.x;
    if (i < DP_) {
        float aq = 0.f, ak = 0.f, av = 0.f;
        for (int m = 0; m < DM_; ++m) {
            float fw = fc1w[i*DM_ + m];
            aq = fmaf(fw, wq[m*DM_ + f], aq);
            ak = fmaf(fw, wk[m*DM_ + f], ak);
            av = fmaf(fw, wv[m*DM_ + f], av);
        }
        g_Wq2[i*DM_ + f] = aq;
        g_Wk2[i*DM_ + f] = ak;
        g_Wv2[i*DM_ + f] = av;
    } else {
        float bq = 0.f, bk = 0.f, bv = 0.f;
        for (int m = 0; m < DM_; ++m) {
            float fb = fc1b[m];
            bq = fmaf(fb, wq[m*DM_ + f], bq);
            bk = fmaf(fb, wk[m*DM_ + f], bk);
            bv = fmaf(fb, wv[m*DM_ + f], bv);
        }
        g_bq[f] = bq; g_bk[f] = bk; g_bv[f] = bv;
    }
}

// ---------------------------------------------------------------------------
// Kernel 0c: Wqs = Wq2@SWG, Wks = Wk2@SWG (+ bqs, bks)
// ---------------------------------------------------------------------------
__global__ __launch_bounds__(128) void wprep3_kernel() {
    int f = threadIdx.x, i = blockIdx.x;
    if (i < DP_) {
        float aq = 0.f, ak = 0.f;
        for (int m = 0; m < DM_; ++m) {
            float s = g_SWG[m*DM_ + f];
            aq = fmaf(g_Wq2[i*DM_ + m], s, aq);
            ak = fmaf(g_Wk2[i*DM_ + m], s, ak);
        }
        g_Wqs[i*DM_ + f] = aq;
        g_Wks[i*DM_ + f] = ak;
    } else {
        float bq = 0.f, bk = 0.f;
        for (int m = 0; m < DM_; ++m) {
            float s = g_SWG[m*DM_ + f];
            bq = fmaf(g_bq[m], s, bq);
            bk = fmaf(g_bk[m], s, bk);
        }
        g_bqs[f] = bq; g_bks[f] = bk;
    }
}

// ---------------------------------------------------------------------------
// Kernel 2: all five projections directly from features (K=64 GEMMs) + kn
// ---------------------------------------------------------------------------
__global__ __launch_bounds__(128) void proj_kernel(const float* __restrict__ feat) {
    __shared__ __align__(16) float sX [DP_*PAD];
    __shared__ __align__(16) float sKc[DM_*PAD];
    int tid = threadIdx.x;
    int r0  = blockIdx.x * 16;

    for (int i = tid; i < 16*DP_; i += 128) {
        int r = i >> 6, c = i & 63;
        sX[c*PAD + r] = __ldcs(&feat[r0*DP_ + i]);
    }
    __syncthreads();

    unsigned long long acc2[8];
    // q
    { float b = g_bq[tid];
#pragma unroll
      for (int j = 0; j < 8; ++j) acc2[j] = pk(b, b); }
    gemm_cm_t<DP_>(g_Wq2, tid, sX, acc2);
#pragma unroll
    for (int j = 0; j < 8; ++j) {
        float2 v = upk(acc2[j]);
        g_Q[(r0 + 2*j  )*DM_ + tid] = v.x;
        g_Q[(r0 + 2*j+1)*DM_ + tid] = v.y;
    }
    // k (also staged col-major for kn)
    { float b = g_bk[tid];
#pragma unroll
      for (int j = 0; j < 8; ++j) acc2[j] = pk(b, b); }
    gemm_cm_t<DP_>(g_Wk2, tid, sX, acc2);
#pragma unroll
    for (int j = 0; j < 8; ++j) {
        float2 v = upk(acc2[j]);
        g_Kf[(r0 + 2*j  )*DM_ + tid] = v.x;
        g_Kf[(r0 + 2*j+1)*DM_ + tid] = v.y;
        sKc[tid*PAD + 2*j]   = v.x;
        sKc[tid*PAD + 2*j+1] = v.y;
    }
    // v
    { float b = g_bv[tid];
#pragma unroll
      for (int j = 0; j < 8; ++j) acc2[j] = pk(b, b); }
    gemm_cm_t<DP_>(g_Wv2, tid, sX, acc2);
#pragma unroll
    for (int j = 0; j < 8; ++j) {
        float2 v = upk(acc2[j]);
        g_Vf[(r0 + 2*j  )*DM_ + tid] = v.x;
        g_Vf[(r0 + 2*j+1)*DM_ + tid] = v.y;
    }
    // QS2
    { float b = g_bqs[tid];
#pragma unroll
      for (int j = 0; j < 8; ++j) acc2[j] = pk(b, b); }
    gemm_cm_t<DP_>(g_Wqs, tid, sX, acc2);
#pragma unroll
    for (int j = 0; j < 8; ++j) {
        float2 v = upk(acc2[j]);
        g_QS2[(r0 + 2*j  )*DM_ + tid] = v.x;
        g_QS2[(r0 + 2*j+1)*DM_ + tid] = v.y;
    }
    // KS2
    { float b = g_bks[tid];
#pragma unroll
      for (int j = 0; j < 8; ++j) acc2[j] = pk(b, b); }
    gemm_cm_t<DP_>(g_Wks, tid, sX, acc2);
#pragma unroll
    for (int j = 0; j < 8; ++j) {
        float2 v = upk(acc2[j]);
        g_KS2[(r0 + 2*j  )*DM_ + tid] = v.x;
        g_KS2[(r0 + 2*j+1)*DM_ + tid] = v.y;
    }
    __syncthreads();

    // kn per row: 8 threads per row
    {
        int k = tid >> 3, lane = tid & 7;
        float k2 = 0.f;
#pragma unroll
        for (int i = 0; i < 16; ++i) {
            float v = sKc[(lane + 8*i)*PAD + k];
            k2 = fmaf(v, v, k2);
        }
#pragma unroll
        for (int off = 4; off; off >>= 1) k2 += __shfl_down_sync(0xffffffffu, k2, off, 8);
        if (lane == 0) g_kn[r0 + k] = fmaxf(sqrtf(k2), 1e-8f);
    }
}

// ---------------------------------------------------------------------------
// Kernel 3: warp-per-query stable top-16 KNN (unchanged from R10).
// ---------------------------------------------------------------------------
#define KNN_WARPS 8
__global__ __launch_bounds__(32*KNN_WARPS) void knn_warp_kernel(const float* __restrict__ xyz) {
    __shared__ float sx[N_];
    __shared__ float sy[N_];
    __shared__ float sz[N_];
    int tid  = threadIdx.x;
    int warp = tid >> 5, lane = tid & 31;
    int blkPerBatch = N_ / KNN_WARPS;          // 512
    int b = blockIdx.x / blkPerBatch;
    int q = (blockIdx.x % blkPerBatch) * KNN_WARPS + warp;
    const float* xb = xyz + (size_t)b * N_ * 3;

    for (int m = tid; m < N_; m += 32*KNN_WARPS) {
        sx[m] = xb[m*3+0]; sy[m] = xb[m*3+1]; sz[m] = xb[m*3+2];
    }
    __syncthreads();

    float qx = sx[q], qy = sy[q], qz = sz[q];
    float qsq = qx*qx + qy*qy + qz*qz;

    unsigned long long cur = ~0ull;
    unsigned long long tau = ~0ull;

#pragma unroll 4
    for (int s = 0; s < N_/32; ++s) {
        int m = s*32 + lane;
        float mx = sx[m], my = sy[m], mz = sz[m];
        float msq = mx*mx + my*my + mz*mz;
        float dot = qx*mx + qy*my + qz*mz;
        float d   = qsq + msq - 2.0f*dot;
        unsigned ub = __float_as_uint(d);
        ub ^= (unsigned)((int)ub >> 31) | 0x80000000u;
        unsigned long long key = ((unsigned long long)ub << 32) | (unsigned)m;

        unsigned ballot = __ballot_sync(0xffffffffu, key < tau);
        while (ballot) {
            int src = __ffs(ballot) - 1;
            ballot &= ballot - 1;
            unsigned long long cb = __shfl_sync(0xffffffffu, key, src);
            if (cb >= tau) continue;
            unsigned less = __ballot_sync(0xffffffffu, cur < cb) & 0xffffu;
            int pos = __popc(less);
            unsigned long long sh = __shfl_up_sync(0xffffffffu, cur, 1);
            if (lane > pos) cur = sh;
            else if (lane == pos) cur = cb;
            tau = __shfl_sync(0xffffffffu, cur, 15);
        }
    }
    if (lane < 16) g_idx[(size_t)(b*N_ + q) * K_ + lane] = (int)(unsigned)cur;
}

// ---------------------------------------------------------------------------
// Kernel 4: fused per-point block. Streaming (__ldcs/__stcs) on all one-touch
// and scattered traffic so the Wp/d2w/g2w weight stream stays L1-resident.
// ---------------------------------------------------------------------------
__global__ __launch_bounds__(128) void fused_kernel(
    const float* __restrict__ xyz,  const float* __restrict__ feat,
    const float* __restrict__ d1w,  const float* __restrict__ d1b,
    const float* __restrict__ d2w,  const float* __restrict__ d2b,
    const float* __restrict__ g2w,  const float* __restrict__ g2b,
    const float* __restrict__ fc2w, const float* __restrict__ fc2b,
    float* __restrict__ out_res,    float* __restrict__ out_attn)
{
    __shared__ __align__(16) float sCM[DM_*PAD];
    __shared__ __align__(16) float sKr[16*DM_];
    __shared__ __align__(16) float sV [16*DM_];
    __shared__ float sQ[DM_];
    __shared__ float sRed[DM_];
    __shared__ float sSim[16];
    __shared__ float sKn[16];
    __shared__ float sRp[16][3];
    __shared__ int   sIdx[16];
    __shared__ float sQn;

    int tid = threadIdx.x;
    int p   = blockIdx.x;
    int b   = p >> 12;
    int base_b = b * N_;

    if (tid < 16) sIdx[tid] = g_idx[(size_t)p * K_ + tid];
    float qf   = __ldcs(&g_Q  [(size_t)p * DM_ + tid]);
    float QS2f = __ldcs(&g_QS2[(size_t)p * DM_ + tid]);
    float uf   = g_u[tid];
    float cbf  = g_cb[tid];
    sQ[tid] = qf;
    __syncthreads();

#pragma unroll
    for (int k = 0; k < 16; ++k) {
        int id = sIdx[k];
        size_t a = (size_t)(base_b + id) * DM_ + tid;
        sKr[k*DM_ + tid] = __ldcs(&g_Kf[a]);
        sV [k*DM_ + tid] = __ldcs(&g_Vf[a]);
    }
    if (tid < 16) {
        int id = sIdx[tid];
        const float* xp = xyz + (size_t)p * 3;
        const float* np = xyz + (size_t)(base_b + id) * 3;
        sRp[tid][0] = xp[0] - np[0];
        sRp[tid][1] = xp[1] - np[1];
        sRp[tid][2] = xp[2] - np[2];
        sKn[tid] = g_kn[base_b + id];
    }

    float v2 = qf * qf;
#pragma unroll
    for (int off = 16; off; off >>= 1) v2 += __shfl_down_sync(0xffffffffu, v2, off);
    if ((tid & 31) == 0) sRed[tid >> 5] = v2;
    __syncthreads();
    if (tid == 0) sQn = fmaxf(sqrtf(sRed[0] + sRed[1] + sRed[2] + sRed[3]), 1e-8f);

    {
        int k = tid >> 3, lane = tid & 7;
        float dp = 0.f;
#pragma unroll
        for (int i = 0; i < 16; ++i) {
            int f = lane + 8*i;
            dp = fmaf(sQ[f], sKr[k*DM_ + f], dp);
        }
#pragma unroll
        for (int off = 4; off; off >>= 1) dp += __shfl_down_sync(0xffffffffu, dp, off, 8);
        if (lane == 0) sSim[k] = dp;
    }
    __syncthreads();
    if (tid < 16) sSim[tid] = sSim[tid] / (sQn * sKn[tid]);

    {
        float w0 = d1w[tid], w1 = d1w[DM_ + tid], w2 = d1w[2*DM_ + tid];
        float bb = d1b[tid];
#pragma unroll
        for (int k = 0; k < 16; ++k) {
            float vv = fmaf(sRp[k][0], w0, fmaf(sRp[k][1], w1, fmaf(sRp[k][2], w2, bb)));
            sCM[tid*PAD + k] = fmaxf(vv, 0.f);
        }
    }
    __syncthreads();

    unsigned long long pos2[8], tac2[8];
    {
        float db   = d2b[tid];
        float base = QS2f + cbf;
#pragma unroll
        for (int j = 0; j < 8; ++j) {
            pos2[j] = pk(db, db);
            int k0 = 2*j;
            float t0 = fmaf(sSim[k0],   uf, base - __ldcs(&g_KS2[(size_t)(base_b + sIdx[k0  ])*DM_ + tid]));
            float t1 = fmaf(sSim[k0+1], uf, base - __ldcs(&g_KS2[(size_t)(base_b + sIdx[k0+1])*DM_ + tid]));
            tac2[j] = pk(t0, t1);
        }
    }
#pragma unroll 2
    for (int c = 0; c < DM_; ++c) {
        float wd = d2w[c*DM_ + tid];
        float wp = g_Wp[c*DM_ + tid];
        unsigned long long wd2 = pk(wd, wd), wp2 = pk(wp, wp);
        const ulonglong2* col = (const ulonglong2*)(sCM + c*PAD);
#pragma unroll
        for (int j = 0; j < 4; ++j) {
            ulonglong2 a = col[j];
            ffma2(pos2[2*j],   a.x, wd2);
            ffma2(pos2[2*j+1], a.y, wd2);
            ffma2(tac2[2*j],   a.x, wp2);
            ffma2(tac2[2*j+1], a.y, wp2);
        }
    }
    __syncthreads();

#pragma unroll
    for (int j = 0; j < 8; ++j) {
        float2 t = upk(tac2[j]);
        sCM[tid*PAD + 2*j]   = fmaxf(t.x, 0.f);
        sCM[tid*PAD + 2*j+1] = fmaxf(t.y, 0.f);
    }
    __syncthreads();

    unsigned long long lac2[8];
    {
        float gb = g2b[tid];
#pragma unroll
        for (int j = 0; j < 8; ++j) lac2[j] = pk(gb, gb);
    }
    gemm_cm_t<DM_>(g2w, tid, sCM, lac2);

    float l[16], posv[16];
#pragma unroll
    for (int j = 0; j < 8; ++j) {
        float2 t = upk(lac2[j]);
        l[2*j] = t.x; l[2*j+1] = t.y;
        float2 pq = upk(pos2[j]);
        posv[2*j] = pq.x; posv[2*j+1] = pq.y;
    }
    const float scale = 1.0f / 11.313708498984760390f;
    float mxv = -3.4e38f;
#pragma unroll
    for (int k = 0; k < 16; ++k) { l[k] *= scale; mxv = fmaxf(mxv, l[k]); }
    float ssum = 0.f;
#pragma unroll
    for (int k = 0; k < 16; ++k) { l[k] = expf(l[k] - mxv); ssum += l[k]; }
    float inv = 1.0f / ssum;
    float resf = 0.f;
#pragma unroll
    for (int k = 0; k < 16; ++k) {
        float a = l[k] * inv;
        __stcs(&out_attn[((size_t)p * K_ + k) * DM_ + tid], a);
        resf = fmaf(a, sV[k*DM_ + tid] + posv[k], resf);
    }
    sRed[tid] = resf;
    __syncthreads();

    if (tid < DP_) {
        float o = fc2b[tid] + __ldcs(&feat[(size_t)p * DP_ + tid]);
#pragma unroll 4
        for (int f = 0; f < DM_; ++f) o = fmaf(sRed[f], fc2w[f*DP_ + tid], o);
        __stcs(&out_res[(size_t)p * DP_ + tid], o);
    }
}

// ---------------------------------------------------------------------------
extern "C" void kernel_launch(void* const* d_in, const int* in_sizes, int n_in,
                              void* d_out, int out_size) {
    const float* xyz   = (const float*)d_in[0];
    const float* feats = (const float*)d_in[1];
    const float* fc1w  = (const float*)d_in[2];
    const float* fc1b  = (const float*)d_in[3];
    const float* fc2w  = (const float*)d_in[4];
    const float* fc2b  = (const float*)d_in[5];
    const float* d1w   = (const float*)d_in[6];
    const float* d1b   = (const float*)d_in[7];
    const float* d2w   = (const float*)d_in[8];
    const float* d2b   = (const float*)d_in[9];
    const float* g1w   = (const float*)d_in[10];
    const float* g1b   = (const float*)d_in[11];
    const float* g2w   = (const float*)d_in[12];
    const float* g2b   = (const float*)d_in[13];
    const float* wqw   = (const float*)d_in[14];
    const float* wkw   = (const float*)d_in[15];
    const float* wvw   = (const float*)d_in[16];
    const float* simw  = (const float*)d_in[17];
    const float* simb  = (const float*)d_in[18];

    float* out      = (float*)d_out;
    float* out_res  = out;                       // (B, N, DP)
    float* out_attn = out + (size_t)B_*N_*DP_;   // (B, N, K, DM)

    wprep1_kernel<<<DM_ + 1, 128>>>(d2w, d2b, g1w, g1b, simw, simb);
    wprep2_kernel<<<DP_ + 1, 128>>>(fc1w, fc1b, wqw, wkw, wvw);
    wprep3_kernel<<<DP_ + 1, 128>>>();
    proj_kernel<<<NPTS/16, 128>>>(feats);
    knn_warp_kernel<<<B_ * (N_/KNN_WARPS), 32*KNN_WARPS>>>(xyz);
    fused_kernel<<<NPTS, 128>>>(xyz, feats, d1w, d1b, d2w, d2b,
                                g2w, g2b, fc2w, fc2b, out_res, out_attn);
}

// round 14
// speedup vs baseline: 2.1346x; 1.0404x over previous
#include <cuda_runtime.h>
#include <math.h>

#define B_  4
#define N_  4096
#define K_  16
#define DP_ 64
#define DM_ 128
#define NPTS (B_*N_)
#define PAD 20   // col-major tile pad: 20 floats = 80B (16B aligned)

// Scratch (device globals: no allocation allowed in kernel_launch)
__device__ float  g_Q  [NPTS*DM_];
__device__ float2 g_KV [NPTS*DM_];   // interleaved (k, v) per (point, channel)
__device__ float  g_QS2[NPTS*DM_];
__device__ float  g_KS2[NPTS*DM_];
__device__ float  g_kn [NPTS];
__device__ int    g_idx[NPTS*K_];
__device__ float  g_Wp [DM_*DM_];   // d2_w @ g1_w
__device__ float  g_SWG[DM_*DM_];   // sim_w[1:] @ g1_w
__device__ float  g_u  [DM_];       // sim_w[0] @ g1_w
__device__ float  g_cb [DM_];       // (sim_b + d2_b) @ g1_w + g1_b
// folded projection weights (K=64)
__device__ float g_Wq2[DP_*DM_];   // fc1w @ wq
__device__ float g_Wk2[DP_*DM_];   // fc1w @ wk
__device__ float g_Wv2[DP_*DM_];   // fc1w @ wv
__device__ float g_Wqs[DP_*DM_];   // fc1w @ wq @ SWG
__device__ float g_Wks[DP_*DM_];   // fc1w @ wk @ SWG
__device__ float g_bq [DM_];       // fc1b @ wq
__device__ float g_bk [DM_];
__device__ float g_bv [DM_];
__device__ float g_bqs[DM_];       // bq @ SWG
__device__ float g_bks[DM_];

// ---------------------------------------------------------------------------
// fp32x2 packed helpers
// ---------------------------------------------------------------------------
__device__ __forceinline__ unsigned long long pk(float x, float y) {
    unsigned long long r;
    asm("mov.b64 %0, {%1, %2};" : "=l"(r) : "f"(x), "f"(y));
    return r;
}
__device__ __forceinline__ void ffma2(unsigned long long& d,
                                      unsigned long long a, unsigned long long b) {
    asm("fma.rn.f32x2 %0, %1, %2, %0;" : "+l"(d) : "l"(a), "l"(b));
}
__device__ __forceinline__ float2 upk(unsigned long long v) {
    float2 r;
    asm("mov.b64 {%0, %1}, %2;" : "=f"(r.x), "=f"(r.y) : "l"(v));
    return r;
}

// ---------------------------------------------------------------------------
// Col-major GEMM micro-kernel: A is 16 rows x KD cols col-major
// (column c at sCM[c*PAD .. +15]). Thread = output column f.
// ---------------------------------------------------------------------------
template<int KD>
__device__ __forceinline__ void gemm_cm_t(const float* __restrict__ W, int f,
                                          const float* sCM,
                                          unsigned long long acc2[8]) {
#pragma unroll 4
    for (int c = 0; c < KD; ++c) {
        float w = W[c*DM_ + f];
        unsigned long long w2 = pk(w, w);
        const ulonglong2* col = (const ulonglong2*)(sCM + c*PAD);
#pragma unroll
        for (int j = 0; j < 4; ++j) {
            ulonglong2 a = col[j];
            ffma2(acc2[2*j],   a.x, w2);
            ffma2(acc2[2*j+1], a.y, w2);
        }
    }
}

// ---------------------------------------------------------------------------
// Kernel 0a: SWG = sim_w[1:]@g1w, Wp = d2w@g1w, u = sim_w[0]@g1w,
//            cb = (sim_b+d2_b)@g1w + g1b
// ---------------------------------------------------------------------------
__global__ __launch_bounds__(128) void wprep1_kernel(
    const float* __restrict__ d2w, const float* __restrict__ d2b,
    const float* __restrict__ g1w, const float* __restrict__ g1b,
    const float* __restrict__ simw, const float* __restrict__ simb)
{
    int f = threadIdx.x, i = blockIdx.x;
    if (i < DM_) {
        float a = 0.f, s = 0.f;
        for (int m = 0; m < DM_; ++m) {
            float g = g1w[m*DM_ + f];
            a = fmaf(d2w[i*DM_ + m], g, a);
            s = fmaf(simw[(1+i)*DM_ + m], g, s);
        }
        g_Wp[i*DM_ + f]  = a;
        g_SWG[i*DM_ + f] = s;
    } else {
        float u = 0.f, c = 0.f;
        for (int m = 0; m < DM_; ++m) {
            float g = g1w[m*DM_ + f];
            u = fmaf(simw[m], g, u);
            c = fmaf(simb[m] + d2b[m], g, c);
        }
        g_u[f]  = u;
        g_cb[f] = c + g1b[f];
    }
}

// ---------------------------------------------------------------------------
// Kernel 0b: Wq2 = fc1w@wq, Wk2 = fc1w@wk, Wv2 = fc1w@wv (+ biases)
// ---------------------------------------------------------------------------
__global__ __launch_bounds__(128) void wprep2_kernel(
    const float* __restrict__ fc1w, const float* __restrict__ fc1b,
    const float* __restrict__ wq, const float* __restrict__ wk,
    const float* __restrict__ wv)
{
    int f = threadIdx.x, i = blockIdx.x;
    if (i < DP_) {
        float aq = 0.f, ak = 0.f, av = 0.f;
        for (int m = 0; m < DM_; ++m) {
            float fw = fc1w[i*DM_ + m];
            aq = fmaf(fw, wq[m*DM_ + f], aq);
            ak = fmaf(fw, wk[m*DM_ + f], ak);
            av = fmaf(fw, wv[m*DM_ + f], av);
        }
        g_Wq2[i*DM_ + f] = aq;
        g_Wk2[i*DM_ + f] = ak;
        g_Wv2[i*DM_ + f] = av;
    } else {
        float bq = 0.f, bk = 0.f, bv = 0.f;
        for (int m = 0; m < DM_; ++m) {
            float fb = fc1b[m];
            bq = fmaf(fb, wq[m*DM_ + f], bq);
            bk = fmaf(fb, wk[m*DM_ + f], bk);
            bv = fmaf(fb, wv[m*DM_ + f], bv);
        }
        g_bq[f] = bq; g_bk[f] = bk; g_bv[f] = bv;
    }
}

// ---------------------------------------------------------------------------
// Kernel 0c: Wqs = Wq2@SWG, Wks = Wk2@SWG (+ bqs, bks)
// ---------------------------------------------------------------------------
__global__ __launch_bounds__(128) void wprep3_kernel() {
    int f = threadIdx.x, i = blockIdx.x;
    if (i < DP_) {
        float aq = 0.f, ak = 0.f;
        for (int m = 0; m < DM_; ++m) {
            float s = g_SWG[m*DM_ + f];
            aq = fmaf(g_Wq2[i*DM_ + m], s, aq);
            ak = fmaf(g_Wk2[i*DM_ + m], s, ak);
        }
        g_Wqs[i*DM_ + f] = aq;
        g_Wks[i*DM_ + f] = ak;
    } else {
        float bq = 0.f, bk = 0.f;
        for (int m = 0; m < DM_; ++m) {
            float s = g_SWG[m*DM_ + f];
            bq = fmaf(g_bq[m], s, bq);
            bk = fmaf(g_bk[m], s, bk);
        }
        g_bqs[f] = bq; g_bks[f] = bk;
    }
}

// ---------------------------------------------------------------------------
// Kernel 2: all five projections directly from features (K=64 GEMMs) + kn.
// k results staged col-major in sKc, then paired with v into g_KV (float2).
// ---------------------------------------------------------------------------
__global__ __launch_bounds__(128) void proj_kernel(const float* __restrict__ feat) {
    __shared__ __align__(16) float sX [DP_*PAD];
    __shared__ __align__(16) float sKc[DM_*PAD];
    int tid = threadIdx.x;
    int r0  = blockIdx.x * 16;

    for (int i = tid; i < 16*DP_; i += 128) {
        int r = i >> 6, c = i & 63;
        sX[c*PAD + r] = __ldcs(&feat[r0*DP_ + i]);
    }
    __syncthreads();

    unsigned long long acc2[8];
    // q
    { float b = g_bq[tid];
#pragma unroll
      for (int j = 0; j < 8; ++j) acc2[j] = pk(b, b); }
    gemm_cm_t<DP_>(g_Wq2, tid, sX, acc2);
#pragma unroll
    for (int j = 0; j < 8; ++j) {
        float2 v = upk(acc2[j]);
        g_Q[(r0 + 2*j  )*DM_ + tid] = v.x;
        g_Q[(r0 + 2*j+1)*DM_ + tid] = v.y;
    }
    // k (staged col-major; written to g_KV after v is computed)
    { float b = g_bk[tid];
#pragma unroll
      for (int j = 0; j < 8; ++j) acc2[j] = pk(b, b); }
    gemm_cm_t<DP_>(g_Wk2, tid, sX, acc2);
#pragma unroll
    for (int j = 0; j < 8; ++j) {
        float2 v = upk(acc2[j]);
        sKc[tid*PAD + 2*j]   = v.x;
        sKc[tid*PAD + 2*j+1] = v.y;
    }
    // v -> pair with k into g_KV
    { float b = g_bv[tid];
#pragma unroll
      for (int j = 0; j < 8; ++j) acc2[j] = pk(b, b); }
    gemm_cm_t<DP_>(g_Wv2, tid, sX, acc2);
#pragma unroll
    for (int j = 0; j < 8; ++j) {
        float2 v = upk(acc2[j]);
        g_KV[(size_t)(r0 + 2*j  )*DM_ + tid] = make_float2(sKc[tid*PAD + 2*j],   v.x);
        g_KV[(size_t)(r0 + 2*j+1)*DM_ + tid] = make_float2(sKc[tid*PAD + 2*j+1], v.y);
    }
    // QS2
    { float b = g_bqs[tid];
#pragma unroll
      for (int j = 0; j < 8; ++j) acc2[j] = pk(b, b); }
    gemm_cm_t<DP_>(g_Wqs, tid, sX, acc2);
#pragma unroll
    for (int j = 0; j < 8; ++j) {
        float2 v = upk(acc2[j]);
        g_QS2[(r0 + 2*j  )*DM_ + tid] = v.x;
        g_QS2[(r0 + 2*j+1)*DM_ + tid] = v.y;
    }
    // KS2
    { float b = g_bks[tid];
#pragma unroll
      for (int j = 0; j < 8; ++j) acc2[j] = pk(b, b); }
    gemm_cm_t<DP_>(g_Wks, tid, sX, acc2);
#pragma unroll
    for (int j = 0; j < 8; ++j) {
        float2 v = upk(acc2[j]);
        g_KS2[(r0 + 2*j  )*DM_ + tid] = v.x;
        g_KS2[(r0 + 2*j+1)*DM_ + tid] = v.y;
    }
    __syncthreads();

    // kn per row: 8 threads per row
    {
        int k = tid >> 3, lane = tid & 7;
        float k2 = 0.f;
#pragma unroll
        for (int i = 0; i < 16; ++i) {
            float v = sKc[(lane + 8*i)*PAD + k];
            k2 = fmaf(v, v, k2);
        }
#pragma unroll
        for (int off = 4; off; off >>= 1) k2 += __shfl_down_sync(0xffffffffu, k2, off, 8);
        if (lane == 0) g_kn[r0 + k] = fmaxf(sqrtf(k2), 1e-8f);
    }
}

// ---------------------------------------------------------------------------
// Kernel 3: warp-per-query stable top-16 KNN (unchanged from R10).
// ---------------------------------------------------------------------------
#define KNN_WARPS 8
__global__ __launch_bounds__(32*KNN_WARPS) void knn_warp_kernel(const float* __restrict__ xyz) {
    __shared__ float sx[N_];
    __shared__ float sy[N_];
    __shared__ float sz[N_];
    int tid  = threadIdx.x;
    int warp = tid >> 5, lane = tid & 31;
    int blkPerBatch = N_ / KNN_WARPS;          // 512
    int b = blockIdx.x / blkPerBatch;
    int q = (blockIdx.x % blkPerBatch) * KNN_WARPS + warp;
    const float* xb = xyz + (size_t)b * N_ * 3;

    for (int m = tid; m < N_; m += 32*KNN_WARPS) {
        sx[m] = xb[m*3+0]; sy[m] = xb[m*3+1]; sz[m] = xb[m*3+2];
    }
    __syncthreads();

    float qx = sx[q], qy = sy[q], qz = sz[q];
    float qsq = qx*qx + qy*qy + qz*qz;

    unsigned long long cur = ~0ull;
    unsigned long long tau = ~0ull;

#pragma unroll 4
    for (int s = 0; s < N_/32; ++s) {
        int m = s*32 + lane;
        float mx = sx[m], my = sy[m], mz = sz[m];
        float msq = mx*mx + my*my + mz*mz;
        float dot = qx*mx + qy*my + qz*mz;
        float d   = qsq + msq - 2.0f*dot;
        unsigned ub = __float_as_uint(d);
        ub ^= (unsigned)((int)ub >> 31) | 0x80000000u;
        unsigned long long key = ((unsigned long long)ub << 32) | (unsigned)m;

        unsigned ballot = __ballot_sync(0xffffffffu, key < tau);
        while (ballot) {
            int src = __ffs(ballot) - 1;
            ballot &= ballot - 1;
            unsigned long long cb = __shfl_sync(0xffffffffu, key, src);
            if (cb >= tau) continue;
            unsigned less = __ballot_sync(0xffffffffu, cur < cb) & 0xffffu;
            int pos = __popc(less);
            unsigned long long sh = __shfl_up_sync(0xffffffffu, cur, 1);
            if (lane > pos) cur = sh;
            else if (lane == pos) cur = cb;
            tau = __shfl_sync(0xffffffffu, cur, 15);
        }
    }
    if (lane < 16) g_idx[(size_t)(b*N_ + q) * K_ + lane] = (int)(unsigned)cur;
}

// ---------------------------------------------------------------------------
// Kernel 4: fused per-point block. launch_bounds(128,6) to lift occupancy;
// unroll-4 dual GEMM; float2 KV gather; streaming policy on one-touch data.
// ---------------------------------------------------------------------------
__global__ __launch_bounds__(128, 6) void fused_kernel(
    const float* __restrict__ xyz,  const float* __restrict__ feat,
    const float* __restrict__ d1w,  const float* __restrict__ d1b,
    const float* __restrict__ d2w,  const float* __restrict__ d2b,
    const float* __restrict__ g2w,  const float* __restrict__ g2b,
    const float* __restrict__ fc2w, const float* __restrict__ fc2b,
    float* __restrict__ out_res,    float* __restrict__ out_attn)
{
    __shared__ __align__(16) float sCM[DM_*PAD];
    __shared__ __align__(16) float sKr[16*DM_];
    __shared__ __align__(16) float sV [16*DM_];
    __shared__ float sQ[DM_];
    __shared__ float sRed[DM_];
    __shared__ float sSim[16];
    __shared__ float sKn[16];
    __shared__ float sRp[16][3];
    __shared__ int   sIdx[16];
    __shared__ float sQn;

    int tid = threadIdx.x;
    int p   = blockIdx.x;
    int b   = p >> 12;
    int base_b = b * N_;

    if (tid < 16) sIdx[tid] = g_idx[(size_t)p * K_ + tid];
    float qf   = __ldcs(&g_Q  [(size_t)p * DM_ + tid]);
    float QS2f = __ldcs(&g_QS2[(size_t)p * DM_ + tid]);
    float uf   = g_u[tid];
    float cbf  = g_cb[tid];
    sQ[tid] = qf;
    __syncthreads();

#pragma unroll
    for (int k = 0; k < 16; ++k) {
        int id = sIdx[k];
        float2 kv = __ldcs(&g_KV[(size_t)(base_b + id) * DM_ + tid]);
        sKr[k*DM_ + tid] = kv.x;
        sV [k*DM_ + tid] = kv.y;
    }
    if (tid < 16) {
        int id = sIdx[tid];
        const float* xp = xyz + (size_t)p * 3;
        const float* np = xyz + (size_t)(base_b + id) * 3;
        sRp[tid][0] = xp[0] - np[0];
        sRp[tid][1] = xp[1] - np[1];
        sRp[tid][2] = xp[2] - np[2];
        sKn[tid] = g_kn[base_b + id];
    }

    float v2 = qf * qf;
#pragma unroll
    for (int off = 16; off; off >>= 1) v2 += __shfl_down_sync(0xffffffffu, v2, off);
    if ((tid & 31) == 0) sRed[tid >> 5] = v2;
    __syncthreads();
    if (tid == 0) sQn = fmaxf(sqrtf(sRed[0] + sRed[1] + sRed[2] + sRed[3]), 1e-8f);

    {
        int k = tid >> 3, lane = tid & 7;
        float dp = 0.f;
#pragma unroll
        for (int i = 0; i < 16; ++i) {
            int f = lane + 8*i;
            dp = fmaf(sQ[f], sKr[k*DM_ + f], dp);
        }
#pragma unroll
        for (int off = 4; off; off >>= 1) dp += __shfl_down_sync(0xffffffffu, dp, off, 8);
        if (lane == 0) sSim[k] = dp;
    }
    __syncthreads();
    if (tid < 16) sSim[tid] = sSim[tid] / (sQn * sKn[tid]);

    {
        float w0 = d1w[tid], w1 = d1w[DM_ + tid], w2 = d1w[2*DM_ + tid];
        float bb = d1b[tid];
#pragma unroll
        for (int k = 0; k < 16; ++k) {
            float vv = fmaf(sRp[k][0], w0, fmaf(sRp[k][1], w1, fmaf(sRp[k][2], w2, bb)));
            sCM[tid*PAD + k] = fmaxf(vv, 0.f);
        }
    }
    __syncthreads();

    unsigned long long pos2[8], tac2[8];
    {
        float db   = d2b[tid];
        float base = QS2f + cbf;
#pragma unroll
        for (int j = 0; j < 8; ++j) {
            pos2[j] = pk(db, db);
            int k0 = 2*j;
            float t0 = fmaf(sSim[k0],   uf, base - __ldcs(&g_KS2[(size_t)(base_b + sIdx[k0  ])*DM_ + tid]));
            float t1 = fmaf(sSim[k0+1], uf, base - __ldcs(&g_KS2[(size_t)(base_b + sIdx[k0+1])*DM_ + tid]));
            tac2[j] = pk(t0, t1);
        }
    }
#pragma unroll 4
    for (int c = 0; c < DM_; ++c) {
        float wd = d2w[c*DM_ + tid];
        float wp = g_Wp[c*DM_ + tid];
        unsigned long long wd2 = pk(wd, wd), wp2 = pk(wp, wp);
        const ulonglong2* col = (const ulonglong2*)(sCM + c*PAD);
#pragma unroll
        for (int j = 0; j < 4; ++j) {
            ulonglong2 a = col[j];
            ffma2(pos2[2*j],   a.x, wd2);
            ffma2(pos2[2*j+1], a.y, wd2);
            ffma2(tac2[2*j],   a.x, wp2);
            ffma2(tac2[2*j+1], a.y, wp2);
        }
    }
    __syncthreads();

#pragma unroll
    for (int j = 0; j < 8; ++j) {
        float2 t = upk(tac2[j]);
        sCM[tid*PAD + 2*j]   = fmaxf(t.x, 0.f);
        sCM[tid*PAD + 2*j+1] = fmaxf(t.y, 0.f);
    }
    __syncthreads();

    unsigned long long lac2[8];
    {
        float gb = g2b[tid];
#pragma unroll
        for (int j = 0; j < 8; ++j) lac2[j] = pk(gb, gb);
    }
    gemm_cm_t<DM_>(g2w, tid, sCM, lac2);

    float l[16], posv[16];
#pragma unroll
    for (int j = 0; j < 8; ++j) {
        float2 t = upk(lac2[j]);
        l[2*j] = t.x; l[2*j+1] = t.y;
        float2 pq = upk(pos2[j]);
        posv[2*j] = pq.x; posv[2*j+1] = pq.y;
    }
    const float scale = 1.0f / 11.313708498984760390f;
    float mxv = -3.4e38f;
#pragma unroll
    for (int k = 0; k < 16; ++k) { l[k] *= scale; mxv = fmaxf(mxv, l[k]); }
    float ssum = 0.f;
#pragma unroll
    for (int k = 0; k < 16; ++k) { l[k] = expf(l[k] - mxv); ssum += l[k]; }
    float inv = 1.0f / ssum;
    float resf = 0.f;
#pragma unroll
    for (int k = 0; k < 16; ++k) {
        float a = l[k] * inv;
        __stcs(&out_attn[((size_t)p * K_ + k) * DM_ + tid], a);
        resf = fmaf(a, sV[k*DM_ + tid] + posv[k], resf);
    }
    sRed[tid] = resf;
    __syncthreads();

    if (tid < DP_) {
        float o = fc2b[tid] + __ldcs(&feat[(size_t)p * DP_ + tid]);
#pragma unroll 4
        for (int f = 0; f < DM_; ++f) o = fmaf(sRed[f], fc2w[f*DP_ + tid], o);
        __stcs(&out_res[(size_t)p * DP_ + tid], o);
    }
}

// ---------------------------------------------------------------------------
extern "C" void kernel_launch(void* const* d_in, const int* in_sizes, int n_in,
                              void* d_out, int out_size) {
    const float* xyz   = (const float*)d_in[0];
    const float* feats = (const float*)d_in[1];
    const float* fc1w  = (const float*)d_in[2];
    const float* fc1b  = (const float*)d_in[3];
    const float* fc2w  = (const float*)d_in[4];
    const float* fc2b  = (const float*)d_in[5];
    const float* d1w   = (const float*)d_in[6];
    const float* d1b   = (const float*)d_in[7];
    const float* d2w   = (const float*)d_in[8];
    const float* d2b   = (const float*)d_in[9];
    const float* g1w   = (const float*)d_in[10];
    const float* g1b   = (const float*)d_in[11];
    const float* g2w   = (const float*)d_in[12];
    const float* g2b   = (const float*)d_in[13];
    const float* wqw   = (const float*)d_in[14];
    const float* wkw   = (const float*)d_in[15];
    const float* wvw   = (const float*)d_in[16];
    const float* simw  = (const float*)d_in[17];
    const float* simb  = (const float*)d_in[18];

    float* out      = (float*)d_out;
    float* out_res  = out;                       // (B, N, DP)
    float* out_attn = out + (size_t)B_*N_*DP_;   // (B, N, K, DM)

    wprep1_kernel<<<DM_ + 1, 128>>>(d2w, d2b, g1w, g1b, simw, simb);
    wprep2_kernel<<<DP_ + 1, 128>>>(fc1w, fc1b, wqw, wkw, wvw);
    wprep3_kernel<<<DP_ + 1, 128>>>();
    proj_kernel<<<NPTS/16, 128>>>(feats);
    knn_warp_kernel<<<B_ * (N_/KNN_WARPS), 32*KNN_WARPS>>>(xyz);
    fused_kernel<<<NPTS, 128>>>(xyz, feats, d1w, d1b, d2w, d2b,
                                g2w, g2b, fc2w, fc2b, out_res, out_attn);
}

// round 17
// speedup vs baseline: 2.1430x; 1.0039x over previous
#include <cuda_runtime.h>
#include <math.h>

#define B_  4
#define N_  4096
#define K_  16
#define DP_ 64
#define DM_ 128
#define NPTS (B_*N_)
#define PAD 20           // col-major tile pad: 20 floats = 80B (16B aligned)
#define CMF (DM_*PAD)    // floats per col-major tile (2560)

// Scratch (device globals: no allocation allowed in kernel_launch)
__device__ float  g_Q  [NPTS*DM_];
__device__ float2 g_KV [NPTS*DM_];   // interleaved (k, v) per (point, channel)
__device__ float  g_QS2[NPTS*DM_];
__device__ float  g_KS2[NPTS*DM_];
__device__ float  g_kn [NPTS];
__device__ int    g_idx[NPTS*K_];
__device__ float  g_Wp [DM_*DM_];   // d2_w @ g1_w
__device__ float  g_SWG[DM_*DM_];   // sim_w[1:] @ g1_w
__device__ float  g_u  [DM_];       // sim_w[0] @ g1_w
__device__ float  g_cb [DM_];       // (sim_b + d2_b) @ g1_w + g1_b
// folded projection weights (K=64)
__device__ float g_Wq2[DP_*DM_];
__device__ float g_Wk2[DP_*DM_];
__device__ float g_Wv2[DP_*DM_];
__device__ float g_Wqs[DP_*DM_];
__device__ float g_Wks[DP_*DM_];
__device__ float g_bq [DM_];
__device__ float g_bk [DM_];
__device__ float g_bv [DM_];
__device__ float g_bqs[DM_];
__device__ float g_bks[DM_];

// ---------------------------------------------------------------------------
// fp32x2 packed helpers
// ---------------------------------------------------------------------------
__device__ __forceinline__ unsigned long long pk(float x, float y) {
    unsigned long long r;
    asm("mov.b64 %0, {%1, %2};" : "=l"(r) : "f"(x), "f"(y));
    return r;
}
__device__ __forceinline__ void ffma2(unsigned long long& d,
                                      unsigned long long a, unsigned long long b) {
    asm("fma.rn.f32x2 %0, %1, %2, %0;" : "+l"(d) : "l"(a), "l"(b));
}
__device__ __forceinline__ float2 upk(unsigned long long v) {
    float2 r;
    asm("mov.b64 {%0, %1}, %2;" : "=f"(r.x), "=f"(r.y) : "l"(v));
    return r;
}

// ---------------------------------------------------------------------------
// Col-major GEMM micro-kernel (proj): A is 16 x KD col-major.
// ---------------------------------------------------------------------------
template<int KD>
__device__ __forceinline__ void gemm_cm_t(const float* __restrict__ W, int f,
                                          const float* sCM,
                                          unsigned long long acc2[8]) {
#pragma unroll 4
    for (int c = 0; c < KD; ++c) {
        float w = W[c*DM_ + f];
        unsigned long long w2 = pk(w, w);
        const ulonglong2* col = (const ulonglong2*)(sCM + c*PAD);
#pragma unroll
        for (int j = 0; j < 4; ++j) {
            ulonglong2 a = col[j];
            ffma2(acc2[2*j],   a.x, w2);
            ffma2(acc2[2*j+1], a.y, w2);
        }
    }
}

// ---------------------------------------------------------------------------
// Kernel 0a/0b/0c: weight folds (unchanged)
// ---------------------------------------------------------------------------
__global__ __launch_bounds__(128) void wprep1_kernel(
    const float* __restrict__ d2w, const float* __restrict__ d2b,
    const float* __restrict__ g1w, const float* __restrict__ g1b,
    const float* __restrict__ simw, const float* __restrict__ simb)
{
    int f = threadIdx.x, i = blockIdx.x;
    if (i < DM_) {
        float a = 0.f, s = 0.f;
        for (int m = 0; m < DM_; ++m) {
            float g = g1w[m*DM_ + f];
            a = fmaf(d2w[i*DM_ + m], g, a);
            s = fmaf(simw[(1+i)*DM_ + m], g, s);
        }
        g_Wp[i*DM_ + f]  = a;
        g_SWG[i*DM_ + f] = s;
    } else {
        float u = 0.f, c = 0.f;
        for (int m = 0; m < DM_; ++m) {
            float g = g1w[m*DM_ + f];
            u = fmaf(simw[m], g, u);
            c = fmaf(simb[m] + d2b[m], g, c);
        }
        g_u[f]  = u;
        g_cb[f] = c + g1b[f];
    }
}

__global__ __launch_bounds__(128) void wprep2_kernel(
    const float* __restrict__ fc1w, const float* __restrict__ fc1b,
    const float* __restrict__ wq, const float* __restrict__ wk,
    const float* __restrict__ wv)
{
    int f = threadIdx.x, i = blockIdx.x;
    if (i < DP_) {
        float aq = 0.f, ak = 0.f, av = 0.f;
        for (int m = 0; m < DM_; ++m) {
            float fw = fc1w[i*DM_ + m];
            aq = fmaf(fw, wq[m*DM_ + f], aq);
            ak = fmaf(fw, wk[m*DM_ + f], ak);
            av = fmaf(fw, wv[m*DM_ + f], av);
        }
        g_Wq2[i*DM_ + f] = aq;
        g_Wk2[i*DM_ + f] = ak;
        g_Wv2[i*DM_ + f] = av;
    } else {
        float bq = 0.f, bk = 0.f, bv = 0.f;
        for (int m = 0; m < DM_; ++m) {
            float fb = fc1b[m];
            bq = fmaf(fb, wq[m*DM_ + f], bq);
            bk = fmaf(fb, wk[m*DM_ + f], bk);
            bv = fmaf(fb, wv[m*DM_ + f], bv);
        }
        g_bq[f] = bq; g_bk[f] = bk; g_bv[f] = bv;
    }
}

__global__ __launch_bounds__(128) void wprep3_kernel() {
    int f = threadIdx.x, i = blockIdx.x;
    if (i < DP_) {
        float aq = 0.f, ak = 0.f;
        for (int m = 0; m < DM_; ++m) {
            float s = g_SWG[m*DM_ + f];
            aq = fmaf(g_Wq2[i*DM_ + m], s, aq);
            ak = fmaf(g_Wk2[i*DM_ + m], s, ak);
        }
        g_Wqs[i*DM_ + f] = aq;
        g_Wks[i*DM_ + f] = ak;
    } else {
        float bq = 0.f, bk = 0.f;
        for (int m = 0; m < DM_; ++m) {
            float s = g_SWG[m*DM_ + f];
            bq = fmaf(g_bq[m], s, bq);
            bk = fmaf(g_bk[m], s, bk);
        }
        g_bqs[f] = bq; g_bks[f] = bk;
    }
}

// ---------------------------------------------------------------------------
// Kernel 2: five projections from features (K=64) + kn (unchanged from R14)
// ---------------------------------------------------------------------------
__global__ __launch_bounds__(128) void proj_kernel(const float* __restrict__ feat) {
    __shared__ __align__(16) float sX [DP_*PAD];
    __shared__ __align__(16) float sKc[DM_*PAD];
    int tid = threadIdx.x;
    int r0  = blockIdx.x * 16;

    for (int i = tid; i < 16*DP_; i += 128) {
        int r = i >> 6, c = i & 63;
        sX[c*PAD + r] = __ldcs(&feat[r0*DP_ + i]);
    }
    __syncthreads();

    unsigned long long acc2[8];
    { float b = g_bq[tid];
#pragma unroll
      for (int j = 0; j < 8; ++j) acc2[j] = pk(b, b); }
    gemm_cm_t<DP_>(g_Wq2, tid, sX, acc2);
#pragma unroll
    for (int j = 0; j < 8; ++j) {
        float2 v = upk(acc2[j]);
        g_Q[(r0 + 2*j  )*DM_ + tid] = v.x;
        g_Q[(r0 + 2*j+1)*DM_ + tid] = v.y;
    }
    { float b = g_bk[tid];
#pragma unroll
      for (int j = 0; j < 8; ++j) acc2[j] = pk(b, b); }
    gemm_cm_t<DP_>(g_Wk2, tid, sX, acc2);
#pragma unroll
    for (int j = 0; j < 8; ++j) {
        float2 v = upk(acc2[j]);
        sKc[tid*PAD + 2*j]   = v.x;
        sKc[tid*PAD + 2*j+1] = v.y;
    }
    { float b = g_bv[tid];
#pragma unroll
      for (int j = 0; j < 8; ++j) acc2[j] = pk(b, b); }
    gemm_cm_t<DP_>(g_Wv2, tid, sX, acc2);
#pragma unroll
    for (int j = 0; j < 8; ++j) {
        float2 v = upk(acc2[j]);
        g_KV[(size_t)(r0 + 2*j  )*DM_ + tid] = make_float2(sKc[tid*PAD + 2*j],   v.x);
        g_KV[(size_t)(r0 + 2*j+1)*DM_ + tid] = make_float2(sKc[tid*PAD + 2*j+1], v.y);
    }
    { float b = g_bqs[tid];
#pragma unroll
      for (int j = 0; j < 8; ++j) acc2[j] = pk(b, b); }
    gemm_cm_t<DP_>(g_Wqs, tid, sX, acc2);
#pragma unroll
    for (int j = 0; j < 8; ++j) {
        float2 v = upk(acc2[j]);
        g_QS2[(r0 + 2*j  )*DM_ + tid] = v.x;
        g_QS2[(r0 + 2*j+1)*DM_ + tid] = v.y;
    }
    { float b = g_bks[tid];
#pragma unroll
      for (int j = 0; j < 8; ++j) acc2[j] = pk(b, b); }
    gemm_cm_t<DP_>(g_Wks, tid, sX, acc2);
#pragma unroll
    for (int j = 0; j < 8; ++j) {
        float2 v = upk(acc2[j]);
        g_KS2[(r0 + 2*j  )*DM_ + tid] = v.x;
        g_KS2[(r0 + 2*j+1)*DM_ + tid] = v.y;
    }
    __syncthreads();

    {
        int k = tid >> 3, lane = tid & 7;
        float k2 = 0.f;
#pragma unroll
        for (int i = 0; i < 16; ++i) {
            float v = sKc[(lane + 8*i)*PAD + k];
            k2 = fmaf(v, v, k2);
        }
#pragma unroll
        for (int off = 4; off; off >>= 1) k2 += __shfl_down_sync(0xffffffffu, k2, off, 8);
        if (lane == 0) g_kn[r0 + k] = fmaxf(sqrtf(k2), 1e-8f);
    }
}

// ---------------------------------------------------------------------------
// Kernel 3: warp-per-query stable top-16 KNN (unchanged from R10).
// ---------------------------------------------------------------------------
#define KNN_WARPS 8
__global__ __launch_bounds__(32*KNN_WARPS) void knn_warp_kernel(const float* __restrict__ xyz) {
    __shared__ float sx[N_];
    __shared__ float sy[N_];
    __shared__ float sz[N_];
    int tid  = threadIdx.x;
    int warp = tid >> 5, lane = tid & 31;
    int blkPerBatch = N_ / KNN_WARPS;
    int b = blockIdx.x / blkPerBatch;
    int q = (blockIdx.x % blkPerBatch) * KNN_WARPS + warp;
    const float* xb = xyz + (size_t)b * N_ * 3;

    for (int m = tid; m < N_; m += 32*KNN_WARPS) {
        sx[m] = xb[m*3+0]; sy[m] = xb[m*3+1]; sz[m] = xb[m*3+2];
    }
    __syncthreads();

    float qx = sx[q], qy = sy[q], qz = sz[q];
    float qsq = qx*qx + qy*qy + qz*qz;

    unsigned long long cur = ~0ull;
    unsigned long long tau = ~0ull;

#pragma unroll 4
    for (int s = 0; s < N_/32; ++s) {
        int m = s*32 + lane;
        float mx = sx[m], my = sy[m], mz = sz[m];
        float msq = mx*mx + my*my + mz*mz;
        float dot = qx*mx + qy*my + qz*mz;
        float d   = qsq + msq - 2.0f*dot;
        unsigned ub = __float_as_uint(d);
        ub ^= (unsigned)((int)ub >> 31) | 0x80000000u;
        unsigned long long key = ((unsigned long long)ub << 32) | (unsigned)m;

        unsigned ballot = __ballot_sync(0xffffffffu, key < tau);
        while (ballot) {
            int src = __ffs(ballot) - 1;
            ballot &= ballot - 1;
            unsigned long long cb = __shfl_sync(0xffffffffu, key, src);
            if (cb >= tau) continue;
            unsigned less = __ballot_sync(0xffffffffu, cur < cb) & 0xffffu;
            int pos = __popc(less);
            unsigned long long sh = __shfl_up_sync(0xffffffffu, cur, 1);
            if (lane > pos) cur = sh;
            else if (lane == pos) cur = cb;
            tau = __shfl_sync(0xffffffffu, cur, 15);
        }
    }
    if (lane < 16) g_idx[(size_t)(b*N_ + q) * K_ + lane] = (int)(unsigned)cur;
}

// ---------------------------------------------------------------------------
// Kernel 4: fused, TWO points per block. Thread f carries both points'
// accumulators; every weight LDG feeds 2x the FMAs. sKr overlays sCM
// (k-rows die before pe1 is born).
// ---------------------------------------------------------------------------
__global__ __launch_bounds__(128, 4) void fused2_kernel(
    const float* __restrict__ xyz,  const float* __restrict__ feat,
    const float* __restrict__ d1w,  const float* __restrict__ d1b,
    const float* __restrict__ d2w,  const float* __restrict__ d2b,
    const float* __restrict__ g2w,  const float* __restrict__ g2b,
    const float* __restrict__ fc2w, const float* __restrict__ fc2b,
    float* __restrict__ out_res,    float* __restrict__ out_attn)
{
    __shared__ __align__(16) float uCM[2*CMF];    // sKr (16*DM) overlaid, then pe1/h col-major
    __shared__ __align__(16) float sV [2*16*DM_];
    __shared__ float sQ  [2*DM_];
    __shared__ float sRed[2*DM_];
    __shared__ float sSim[2][16];
    __shared__ float sKn [2][16];
    __shared__ float sRp [2][16][3];
    __shared__ int   sIdx[2][16];
    __shared__ float sQn [2];

    int tid = threadIdx.x;
    int p0  = blockIdx.x * 2;
    int b   = p0 >> 12;
    int base_b = b * N_;

    if (tid < 32) {
        int pp = tid >> 4, kk = tid & 15;
        sIdx[pp][kk] = g_idx[(size_t)(p0 + pp) * K_ + kk];
    }
    float qf[2], QS2f[2];
#pragma unroll
    for (int pp = 0; pp < 2; ++pp) {
        qf[pp]   = __ldcs(&g_Q  [(size_t)(p0+pp) * DM_ + tid]);
        QS2f[pp] = __ldcs(&g_QS2[(size_t)(p0+pp) * DM_ + tid]);
        sQ[pp*DM_ + tid] = qf[pp];
    }
    float uf  = g_u[tid];
    float cbf = g_cb[tid];
    __syncthreads();                                   // S1: sIdx, sQ visible

    // gather k (into uCM overlay) and v
#pragma unroll
    for (int pp = 0; pp < 2; ++pp) {
        float* sKr = uCM + pp*CMF;
#pragma unroll
        for (int k = 0; k < 16; ++k) {
            int id = sIdx[pp][k];
            float2 kv = __ldcs(&g_KV[(size_t)(base_b + id) * DM_ + tid]);
            sKr[k*DM_ + tid]           = kv.x;
            sV [pp*16*DM_ + k*DM_ + tid] = kv.y;
        }
    }
    if (tid < 32) {
        int pp = tid >> 4, kk = tid & 15;
        int id = sIdx[pp][kk];
        const float* xp = xyz + (size_t)(p0+pp) * 3;
        const float* np = xyz + (size_t)(base_b + id) * 3;
        sRp[pp][kk][0] = xp[0] - np[0];
        sRp[pp][kk][1] = xp[1] - np[1];
        sRp[pp][kk][2] = xp[2] - np[2];
        sKn[pp][kk] = g_kn[base_b + id];
    }

    // |q|^2 partials (both points)
    {
        float v0 = qf[0]*qf[0], v1 = qf[1]*qf[1];
#pragma unroll
        for (int off = 16; off; off >>= 1) {
            v0 += __shfl_down_sync(0xffffffffu, v0, off);
            v1 += __shfl_down_sync(0xffffffffu, v1, off);
        }
        if ((tid & 31) == 0) { sRed[tid >> 5] = v0; sRed[DM_ + (tid >> 5)] = v1; }
    }
    __syncthreads();                                   // S2: gathers + partials visible
    if (tid < 2)
        sQn[tid] = fmaxf(sqrtf(sRed[tid*DM_] + sRed[tid*DM_+1] + sRed[tid*DM_+2] + sRed[tid*DM_+3]), 1e-8f);

    // dot(q, k_j): 8 threads per neighbor, per point
#pragma unroll
    for (int pp = 0; pp < 2; ++pp) {
        const float* sKr = uCM + pp*CMF;
        int k = tid >> 3, lane = tid & 7;
        float dp = 0.f;
#pragma unroll
        for (int i = 0; i < 16; ++i) {
            int f = lane + 8*i;
            dp = fmaf(sQ[pp*DM_ + f], sKr[k*DM_ + f], dp);
        }
#pragma unroll
        for (int off = 4; off; off >>= 1) dp += __shfl_down_sync(0xffffffffu, dp, off, 8);
        if (lane == 0) sSim[pp][k] = dp;
    }
    __syncthreads();                                   // S3: dots done; sKr dead

    if (tid < 32) {
        int pp = tid >> 4, kk = tid & 15;
        sSim[pp][kk] = sSim[pp][kk] / (sQn[pp] * sKn[pp][kk]);
    }

    // pe1 = relu(rel_pos@d1 + b) into col-major uCM (overwrites sKr region)
    {
        float w0 = d1w[tid], w1 = d1w[DM_ + tid], w2 = d1w[2*DM_ + tid];
        float bb = d1b[tid];
#pragma unroll
        for (int pp = 0; pp < 2; ++pp) {
            float* sCM = uCM + pp*CMF;
#pragma unroll
            for (int k = 0; k < 16; ++k) {
                float vv = fmaf(sRp[pp][k][0], w0, fmaf(sRp[pp][k][1], w1, fmaf(sRp[pp][k][2], w2, bb)));
                sCM[tid*PAD + k] = fmaxf(vv, 0.f);
            }
        }
    }
    __syncthreads();                                   // S4: pe1 + normalized sSim ready

    // dual GEMM for both points: pos += pe1@d2w ; t += pe1@Wp
    unsigned long long pos2[2][8], tac2[2][8];
    {
        float db = d2b[tid];
#pragma unroll
        for (int pp = 0; pp < 2; ++pp) {
            float base = QS2f[pp] + cbf;
#pragma unroll
            for (int j = 0; j < 8; ++j) {
                pos2[pp][j] = pk(db, db);
                int k0 = 2*j;
                float t0 = fmaf(sSim[pp][k0],   uf, base - __ldcs(&g_KS2[(size_t)(base_b + sIdx[pp][k0  ])*DM_ + tid]));
                float t1 = fmaf(sSim[pp][k0+1], uf, base - __ldcs(&g_KS2[(size_t)(base_b + sIdx[pp][k0+1])*DM_ + tid]));
                tac2[pp][j] = pk(t0, t1);
            }
        }
    }
#pragma unroll 4
    for (int c = 0; c < DM_; ++c) {
        float wd = d2w[c*DM_ + tid];
        float wp = g_Wp[c*DM_ + tid];
        unsigned long long wd2 = pk(wd, wd), wp2 = pk(wp, wp);
#pragma unroll
        for (int pp = 0; pp < 2; ++pp) {
            const ulonglong2* col = (const ulonglong2*)(uCM + pp*CMF + c*PAD);
#pragma unroll
            for (int j = 0; j < 4; ++j) {
                ulonglong2 a = col[j];
                ffma2(pos2[pp][2*j],   a.x, wd2);
                ffma2(pos2[pp][2*j+1], a.y, wd2);
                ffma2(tac2[pp][2*j],   a.x, wp2);
                ffma2(tac2[pp][2*j+1], a.y, wp2);
            }
        }
    }
    __syncthreads();                                   // S5: pe1 reads done

    // h = relu(t) into uCM
#pragma unroll
    for (int pp = 0; pp < 2; ++pp) {
        float* sCM = uCM + pp*CMF;
#pragma unroll
        for (int j = 0; j < 8; ++j) {
            float2 t = upk(tac2[pp][j]);
            sCM[tid*PAD + 2*j]   = fmaxf(t.x, 0.f);
            sCM[tid*PAD + 2*j+1] = fmaxf(t.y, 0.f);
        }
    }
    __syncthreads();                                   // S6

    // logits = h @ g2 + g2b (both points share W loads)
    unsigned long long lac2[2][8];
    {
        float gb = g2b[tid];
#pragma unroll
        for (int pp = 0; pp < 2; ++pp)
#pragma unroll
            for (int j = 0; j < 8; ++j) lac2[pp][j] = pk(gb, gb);
    }
#pragma unroll 4
    for (int c = 0; c < DM_; ++c) {
        float w = g2w[c*DM_ + tid];
        unsigned long long w2 = pk(w, w);
#pragma unroll
        for (int pp = 0; pp < 2; ++pp) {
            const ulonglong2* col = (const ulonglong2*)(uCM + pp*CMF + c*PAD);
#pragma unroll
            for (int j = 0; j < 4; ++j) {
                ulonglong2 a = col[j];
                ffma2(lac2[pp][2*j],   a.x, w2);
                ffma2(lac2[pp][2*j+1], a.y, w2);
            }
        }
    }

    // tail per point: softmax over k, attn store, res accumulate
    const float scale = 1.0f / 11.313708498984760390f;
#pragma unroll
    for (int pp = 0; pp < 2; ++pp) {
        float l[16], posv[16];
#pragma unroll
        for (int j = 0; j < 8; ++j) {
            float2 t = upk(lac2[pp][j]);
            l[2*j] = t.x; l[2*j+1] = t.y;
            float2 pq = upk(pos2[pp][j]);
            posv[2*j] = pq.x; posv[2*j+1] = pq.y;
        }
        float mxv = -3.4e38f;
#pragma unroll
        for (int k = 0; k < 16; ++k) { l[k] *= scale; mxv = fmaxf(mxv, l[k]); }
        float ssum = 0.f;
#pragma unroll
        for (int k = 0; k < 16; ++k) { l[k] = expf(l[k] - mxv); ssum += l[k]; }
        float inv = 1.0f / ssum;
        float resf = 0.f;
#pragma unroll
        for (int k = 0; k < 16; ++k) {
            float a = l[k] * inv;
            __stcs(&out_attn[((size_t)(p0+pp) * K_ + k) * DM_ + tid], a);
            resf = fmaf(a, sV[pp*16*DM_ + k*DM_ + tid] + posv[k], resf);
        }
        sRed[pp*DM_ + tid] = resf;
    }
    __syncthreads();                                   // S7

    // out = res @ fc2 + fc2_b + features  (lower 64 threads -> pp0, upper -> pp1)
    {
        int pp = tid >> 6;
        int f  = tid & 63;
        float o = fc2b[f] + __ldcs(&feat[(size_t)(p0+pp) * DP_ + f]);
        const float* r = sRed + pp*DM_;
#pragma unroll 4
        for (int m = 0; m < DM_; ++m) o = fmaf(r[m], fc2w[m*DP_ + f], o);
        __stcs(&out_res[(size_t)(p0+pp) * DP_ + f], o);
    }
}

// ---------------------------------------------------------------------------
extern "C" void kernel_launch(void* const* d_in, const int* in_sizes, int n_in,
                              void* d_out, int out_size) {
    const float* xyz   = (const float*)d_in[0];
    const float* feats = (const float*)d_in[1];
    const float* fc1w  = (const float*)d_in[2];
    const float* fc1b  = (const float*)d_in[3];
    const float* fc2w  = (const float*)d_in[4];
    const float* fc2b  = (const float*)d_in[5];
    const float* d1w   = (const float*)d_in[6];
    const float* d1b   = (const float*)d_in[7];
    const float* d2w   = (const float*)d_in[8];
    const float* d2b   = (const float*)d_in[9];
    const float* g1w   = (const float*)d_in[10];
    const float* g1b   = (const float*)d_in[11];
    const float* g2w   = (const float*)d_in[12];
    const float* g2b   = (const float*)d_in[13];
    const float* wqw   = (const float*)d_in[14];
    const float* wkw   = (const float*)d_in[15];
    const float* wvw   = (const float*)d_in[16];
    const float* simw  = (const float*)d_in[17];
    const float* simb  = (const float*)d_in[18];

    float* out      = (float*)d_out;
    float* out_res  = out;                       // (B, N, DP)
    float* out_attn = out + (size_t)B_*N_*DP_;   // (B, N, K, DM)

    wprep1_kernel<<<DM_ + 1, 128>>>(d2w, d2b, g1w, g1b, simw, simb);
    wprep2_kernel<<<DP_ + 1, 128>>>(fc1w, fc1b, wqw, wkw, wvw);
    wprep3_kernel<<<DP_ + 1, 128>>>();
    proj_kernel<<<NPTS/16, 128>>>(feats);
    knn_warp_kernel<<<B_ * (N_/KNN_WARPS), 32*KNN_WARPS>>>(xyz);
    fused2_kernel<<<NPTS/2, 128>>>(xyz, feats, d1w, d1b, d2w, d2b,
                                   g2w, g2b, fc2w, fc2b, out_res, out_attn);
}